// round 1
// baseline (speedup 1.0000x reference)
#include <cuda_runtime.h>
#include <math.h>

// Problem constants
#define BB 4
#define SS 2048
#define DD 1024
#define HH 16
#define DH 64
#define MROWS (BB * SS)      // 8192
#define N1 (3 * DD)          // 3072

// Scratch (allocation-free: device globals)
__device__ float g_qkv[(size_t)MROWS * N1];   // [B*S, 3D]
__device__ float g_att[(size_t)MROWS * DD];   // [B*S, D]

// ---------------------------------------------------------------------------
// C[M,N] = A[M,K] @ B[N,K]^T + bias[N]   (both A and B K-major / row-major)
// 128x128 block tile, BK=8, 256 threads, 8x8 per-thread microtile.
// ---------------------------------------------------------------------------
__global__ __launch_bounds__(256) void sgemm_nt_bias(
    const float* __restrict__ A, const float* __restrict__ Bm,
    const float* __restrict__ bias, float* __restrict__ C,
    int M, int N, int K)
{
    const int BK = 8;
    __shared__ float As[BK][132];   // [k][m], pad 132 -> conflict-free transpose
    __shared__ float Bs[BK][132];   // [k][n]

    int tid = threadIdx.x;
    int tx = tid % 16;          // 0..15 -> N direction
    int ty = tid / 16;          // 0..15 -> M direction
    int bm = blockIdx.y * 128;
    int bn = blockIdx.x * 128;

    int lrow = tid >> 1;        // 0..127
    int lseg = (tid & 1) * 4;   // 0 or 4

    float acc[8][8];
    #pragma unroll
    for (int i = 0; i < 8; i++)
        #pragma unroll
        for (int j = 0; j < 8; j++) acc[i][j] = 0.f;

    const float* Aptr = A + (size_t)(bm + lrow) * K + lseg;
    const float* Bptr = Bm + (size_t)(bn + lrow) * K + lseg;

    for (int k0 = 0; k0 < K; k0 += BK) {
        float4 av = *(const float4*)(Aptr + k0);
        float4 bv = *(const float4*)(Bptr + k0);
        As[lseg + 0][lrow] = av.x; As[lseg + 1][lrow] = av.y;
        As[lseg + 2][lrow] = av.z; As[lseg + 3][lrow] = av.w;
        Bs[lseg + 0][lrow] = bv.x; Bs[lseg + 1][lrow] = bv.y;
        Bs[lseg + 2][lrow] = bv.z; Bs[lseg + 3][lrow] = bv.w;
        __syncthreads();

        #pragma unroll
        for (int kk = 0; kk < BK; kk++) {
            float ar[8], br[8];
            #pragma unroll
            for (int i = 0; i < 8; i++) ar[i] = As[kk][ty * 8 + i];
            #pragma unroll
            for (int j = 0; j < 8; j++) br[j] = Bs[kk][tx * 8 + j];
            #pragma unroll
            for (int i = 0; i < 8; i++)
                #pragma unroll
                for (int j = 0; j < 8; j++)
                    acc[i][j] += ar[i] * br[j];
        }
        __syncthreads();
    }

    #pragma unroll
    for (int i = 0; i < 8; i++) {
        int row = bm + ty * 8 + i;
        #pragma unroll
        for (int j = 0; j < 8; j++) {
            int col = bn + tx * 8 + j;
            C[(size_t)row * N + col] = acc[i][j] + bias[col];
        }
    }
}

// ---------------------------------------------------------------------------
// Flash attention over g_qkv -> g_att.
// Block = (q-tile of 64 rows, head h, batch b), 64 threads, 1 q-row/thread.
// Online softmax, causal tiles skipped.
// qkv layout: [b, s, 3D] with q at [0,D), k at [D,2D), v at [2D,3D),
// head h occupying columns h*64..h*64+63 of each third.
// ---------------------------------------------------------------------------
__global__ __launch_bounds__(64) void flash_attn(const int* __restrict__ causal_flag)
{
    __shared__ float4 Ks[64][16];   // [k-row][d/4]
    __shared__ float4 Vs[64][16];
    __shared__ float  Sc[64][64];   // [j][t] scores; lane-indexed minor -> conflict-free

    int qt = blockIdx.x;   // q tile, 0..31
    int h  = blockIdx.y;
    int b  = blockIdx.z;
    int t  = threadIdx.x;  // 0..63, owns q row r
    int causal = *causal_flag;

    int r = qt * 64 + t;
    const float* qbase = g_qkv + (size_t)(b * SS + r) * N1 + h * DH;
    float4 q[16];
    #pragma unroll
    for (int i = 0; i < 16; i++) q[i] = *(const float4*)(qbase + i * 4);

    float m = -INFINITY, l = 0.f;
    float o[64];
    #pragma unroll
    for (int d = 0; d < 64; d++) o[d] = 0.f;

    int ktmax = causal ? qt : (SS / 64 - 1);
    for (int kt = 0; kt <= ktmax; kt++) {
        // Cooperative coalesced K/V tile load (16 float4 per thread each)
        const float* kbase = g_qkv + (size_t)(b * SS + kt * 64) * N1 + DD + h * DH;
        const float* vbase = kbase + DD;
        #pragma unroll
        for (int i = 0; i < 16; i++) {
            int fid = i * 64 + t;       // 0..1023
            int row = fid >> 4;
            int c4  = fid & 15;
            Ks[row][c4] = *(const float4*)(kbase + (size_t)row * N1 + c4 * 4);
            Vs[row][c4] = *(const float4*)(vbase + (size_t)row * N1 + c4 * 4);
        }
        __syncthreads();

        // Pass 1: scores + running max
        float mnew = m;
        #pragma unroll 4
        for (int j = 0; j < 64; j++) {
            float dot = 0.f;
            #pragma unroll
            for (int i = 0; i < 16; i++) {
                float4 kk = Ks[j][i];
                dot += q[i].x * kk.x + q[i].y * kk.y
                     + q[i].z * kk.z + q[i].w * kk.w;
            }
            dot *= 0.125f;                                  // 1/sqrt(64)
            if (causal && (kt * 64 + j > r)) dot = -INFINITY;
            Sc[j][t] = dot;
            mnew = fmaxf(mnew, dot);
        }

        // Rescale running accumulators
        float scale = __expf(m - mnew);   // m=-inf on first tile -> 0
        l *= scale;
        #pragma unroll
        for (int d = 0; d < 64; d++) o[d] *= scale;

        // Pass 2: p = exp(s - mnew), accumulate p @ V
        #pragma unroll 2
        for (int j = 0; j < 64; j++) {
            float p = __expf(Sc[j][t] - mnew);   // masked -> exp(-inf)=0
            l += p;
            #pragma unroll
            for (int i = 0; i < 16; i++) {
                float4 vv = Vs[j][i];
                o[i * 4 + 0] += p * vv.x;
                o[i * 4 + 1] += p * vv.y;
                o[i * 4 + 2] += p * vv.z;
                o[i * 4 + 3] += p * vv.w;
            }
        }
        m = mnew;
        __syncthreads();
    }

    float inv = 1.f / l;
    float* obase = g_att + (size_t)(b * SS + r) * DD + h * DH;
    #pragma unroll
    for (int i = 0; i < 16; i++) {
        float4 ov = make_float4(o[i * 4 + 0] * inv, o[i * 4 + 1] * inv,
                                o[i * 4 + 2] * inv, o[i * 4 + 3] * inv);
        *(float4*)(obase + i * 4) = ov;
    }
}

// ---------------------------------------------------------------------------
extern "C" void kernel_launch(void* const* d_in, const int* in_sizes, int n_in,
                              void* d_out, int out_size)
{
    const float* x     = (const float*)d_in[0];
    const float* w_in  = (const float*)d_in[1];
    const float* b_in  = (const float*)d_in[2];
    const float* w_out = (const float*)d_in[3];
    const float* b_out = (const float*)d_in[4];
    const int*   cmask = (const int*)d_in[5];
    float* out = (float*)d_out;

    float *qkv, *att;
    cudaGetSymbolAddress((void**)&qkv, g_qkv);
    cudaGetSymbolAddress((void**)&att, g_att);

    // 1) QKV projection: [8192,1024] @ [3072,1024]^T + b_in -> [8192,3072]
    dim3 g1(N1 / 128, MROWS / 128);
    sgemm_nt_bias<<<g1, 256>>>(x, w_in, b_in, qkv, MROWS, N1, DD);

    // 2) Causal multi-head flash attention -> g_att [8192,1024]
    dim3 g2(SS / 64, HH, BB);
    flash_attn<<<g2, 64>>>(cmask);

    // 3) Output projection: [8192,1024] @ [1024,1024]^T + b_out -> out
    dim3 g3(DD / 128, MROWS / 128);
    sgemm_nt_bias<<<g3, 256>>>(att, w_out, b_out, out, MROWS, DD, DD);
}

// round 3
// speedup vs baseline: 1.6628x; 1.6628x over previous
#include <cuda_runtime.h>
#include <math.h>
#include <stdint.h>

// Problem constants
#define BB 4
#define SS 2048
#define DD 1024
#define HH 16
#define DH 64
#define MROWS (BB * SS)      // 8192
#define N1 (3 * DD)          // 3072

// Scratch (allocation-free: device globals)
__device__ float g_qkv[(size_t)MROWS * N1];   // [B*S, 3D]
__device__ float g_att[(size_t)MROWS * DD];   // [B*S, D]  (tf32-rounded)
__device__ float g_xr [(size_t)MROWS * DD];   // x rounded to tf32
__device__ float g_w1r[(size_t)N1 * DD];      // w_in rounded
__device__ float g_w2r[(size_t)DD * DD];      // w_out rounded

// ===========================================================================
// helpers
// ===========================================================================
__device__ __forceinline__ uint32_t smem_u32(const void* p) {
    uint32_t a;
    asm("{ .reg .u64 t; cvta.to.shared.u64 t, %1; cvt.u32.u64 %0, t; }"
        : "=r"(a) : "l"(p));
    return a;
}
__device__ __forceinline__ float tf32_rna(float x) {
    uint32_t u;
    asm("cvt.rna.tf32.f32 %0, %1;" : "=r"(u) : "f"(x));
    return __uint_as_float(u);
}

#define CP_A16(dst, src) \
    asm volatile("cp.async.cg.shared.global [%0], [%1], 16;" \
                 :: "r"(dst), "l"(src) : "memory")
#define CP_COMMIT() asm volatile("cp.async.commit_group;" ::: "memory")
#define CP_WAIT1()  asm volatile("cp.async.wait_group 1;" ::: "memory")
#define CP_WAIT0()  asm volatile("cp.async.wait_group 0;" ::: "memory")

// ===========================================================================
// tf32 rounding prep kernel (vectorized)
// ===========================================================================
__global__ void round_tf32(const float* __restrict__ s, float* __restrict__ d, int n4)
{
    int i = blockIdx.x * blockDim.x + threadIdx.x;
    if (i < n4) {
        float4 v = ((const float4*)s)[i];
        v.x = tf32_rna(v.x); v.y = tf32_rna(v.y);
        v.z = tf32_rna(v.z); v.w = tf32_rna(v.w);
        ((float4*)d)[i] = v;
    }
}

// ===========================================================================
// tf32 mma.sync GEMM: C[M,N] = A[M,K] @ B[N,K]^T + bias[N]
// CTA 128x128, BK=32, 3-stage cp.async, 8 warps (4 M x 2 N), warp tile 32x64.
// Inputs must already be tf32-exact fp32.
// ===========================================================================
#define STAGES  3
#define BKC     32
#define PAD_S   36                       // smem row stride (floats)
#define TILE_F  (128 * PAD_S)            // floats per operand tile
#define STAGE_F (2 * TILE_F)             // A + B
#define GSMEM_BYTES (STAGES * STAGE_F * 4)   // 110592

__device__ __forceinline__ void compute_chunk(
    const float* __restrict__ As, const float* __restrict__ Bs,
    int wm, int wn, int g, int t, float acc[2][8][4])
{
    #pragma unroll
    for (int ks = 0; ks < 4; ks++) {
        const int kc = ks * 8;
        uint32_t af[2][4];
        #pragma unroll
        for (int mt = 0; mt < 2; mt++) {
            const float* ar = As + (wm * 32 + mt * 16 + g) * PAD_S + kc;
            af[mt][0] = __float_as_uint(ar[t]);
            af[mt][1] = __float_as_uint(ar[8 * PAD_S + t]);
            af[mt][2] = __float_as_uint(ar[t + 4]);
            af[mt][3] = __float_as_uint(ar[8 * PAD_S + t + 4]);
        }
        uint32_t bf[8][2];
        #pragma unroll
        for (int nt = 0; nt < 8; nt++) {
            const float* br = Bs + (wn * 64 + nt * 8 + g) * PAD_S + kc;
            bf[nt][0] = __float_as_uint(br[t]);
            bf[nt][1] = __float_as_uint(br[t + 4]);
        }
        #pragma unroll
        for (int mt = 0; mt < 2; mt++)
            #pragma unroll
            for (int nt = 0; nt < 8; nt++)
                asm volatile(
                    "mma.sync.aligned.m16n8k8.row.col.f32.tf32.tf32.f32 "
                    "{%0,%1,%2,%3}, {%4,%5,%6,%7}, {%8,%9}, {%0,%1,%2,%3};"
                    : "+f"(acc[mt][nt][0]), "+f"(acc[mt][nt][1]),
                      "+f"(acc[mt][nt][2]), "+f"(acc[mt][nt][3])
                    : "r"(af[mt][0]), "r"(af[mt][1]),
                      "r"(af[mt][2]), "r"(af[mt][3]),
                      "r"(bf[nt][0]), "r"(bf[nt][1]));
    }
}

__global__ __launch_bounds__(256, 2) void gemm_tf32mma(
    const float* __restrict__ A, const float* __restrict__ Bm,
    const float* __restrict__ bias, float* __restrict__ C,
    int M, int N, int K)
{
    extern __shared__ float sm[];
    const uint32_t smb = smem_u32(sm);
    const int tid  = threadIdx.x;
    const int lane = tid & 31, wid = tid >> 5;
    const int g = lane >> 2, t = lane & 3;
    const int wm = wid & 3, wn = wid >> 2;
    const int bm = blockIdx.y * 128, bn = blockIdx.x * 128;

    // cp.async source layout: thread -> rows lrow+32i, float4-col lc4
    const int lrow = tid >> 3;
    const int lc4  = tid & 7;
    const float* a0 = A + (size_t)(bm + lrow) * K + lc4 * 4;
    const float* a1 = a0 + (size_t)32 * K;
    const float* a2 = a0 + (size_t)64 * K;
    const float* a3 = a0 + (size_t)96 * K;
    const ptrdiff_t ab = (Bm + (size_t)(bn + lrow) * K + lc4 * 4) - a0;

    const uint32_t dA = smb + (uint32_t)((lrow * PAD_S + lc4 * 4) * 4);

    float acc[2][8][4];
    #pragma unroll
    for (int mt = 0; mt < 2; mt++)
        #pragma unroll
        for (int nt = 0; nt < 8; nt++)
            #pragma unroll
            for (int r = 0; r < 4; r++) acc[mt][nt][r] = 0.f;

#define ISSUE_CHUNK(c, s) do { \
    uint32_t _b = dA + (uint32_t)(s) * (STAGE_F * 4); \
    const float* _p0 = a0 + (c) * BKC; \
    const float* _p1 = a1 + (c) * BKC; \
    const float* _p2 = a2 + (c) * BKC; \
    const float* _p3 = a3 + (c) * BKC; \
    CP_A16(_b,                       _p0); \
    CP_A16(_b + 32 * PAD_S * 4,      _p1); \
    CP_A16(_b + 64 * PAD_S * 4,      _p2); \
    CP_A16(_b + 96 * PAD_S * 4,      _p3); \
    CP_A16(_b + TILE_F * 4,                  _p0 + ab); \
    CP_A16(_b + TILE_F * 4 + 32 * PAD_S * 4, _p1 + ab); \
    CP_A16(_b + TILE_F * 4 + 64 * PAD_S * 4, _p2 + ab); \
    CP_A16(_b + TILE_F * 4 + 96 * PAD_S * 4, _p3 + ab); \
    CP_COMMIT(); \
} while (0)

    const int NCH = K / BKC;
    ISSUE_CHUNK(0, 0);
    ISSUE_CHUNK(1, 1);

    for (int c = 0; c < NCH; c++) {
        if (c + 1 < NCH) { CP_WAIT1(); } else { CP_WAIT0(); }
        __syncthreads();
        if (c + 2 < NCH) ISSUE_CHUNK(c + 2, (c + 2) % STAGES);
        const float* As = sm + (c % STAGES) * STAGE_F;
        compute_chunk(As, As + TILE_F, wm, wn, g, t, acc);
    }
#undef ISSUE_CHUNK

    // Epilogue: c0,c1 at (row g, col t*2..+1); c2,c3 at row g+8
    const int col0 = bn + wn * 64;
    #pragma unroll
    for (int mt = 0; mt < 2; mt++) {
        #pragma unroll
        for (int h = 0; h < 2; h++) {
            int row = bm + wm * 32 + mt * 16 + g + h * 8;
            float* cp = C + (size_t)row * N + col0;
            #pragma unroll
            for (int nt = 0; nt < 8; nt++) {
                int cc = nt * 8 + t * 2;
                float2 bz = *(const float2*)(bias + col0 + cc);
                float2 v;
                v.x = acc[mt][nt][h * 2 + 0] + bz.x;
                v.y = acc[mt][nt][h * 2 + 1] + bz.y;
                *(float2*)(cp + cc) = v;
            }
        }
    }
}

// ---------------------------------------------------------------------------
// Flash attention over g_qkv -> g_att (fp32; output rounded to tf32 for GEMM3)
// ---------------------------------------------------------------------------
__global__ __launch_bounds__(64) void flash_attn(const int* __restrict__ causal_flag)
{
    __shared__ float4 Ks[64][16];
    __shared__ float4 Vs[64][16];
    __shared__ float  Sc[64][64];

    int qt = blockIdx.x;
    int h  = blockIdx.y;
    int b  = blockIdx.z;
    int t  = threadIdx.x;
    int causal = *causal_flag;

    int r = qt * 64 + t;
    const float* qbase = g_qkv + (size_t)(b * SS + r) * N1 + h * DH;
    float4 q[16];
    #pragma unroll
    for (int i = 0; i < 16; i++) q[i] = *(const float4*)(qbase + i * 4);

    float m = -INFINITY, l = 0.f;
    float o[64];
    #pragma unroll
    for (int d = 0; d < 64; d++) o[d] = 0.f;

    int ktmax = causal ? qt : (SS / 64 - 1);
    for (int kt = 0; kt <= ktmax; kt++) {
        const float* kbase = g_qkv + (size_t)(b * SS + kt * 64) * N1 + DD + h * DH;
        const float* vbase = kbase + DD;
        #pragma unroll
        for (int i = 0; i < 16; i++) {
            int fid = i * 64 + t;
            int row = fid >> 4;
            int c4  = fid & 15;
            Ks[row][c4] = *(const float4*)(kbase + (size_t)row * N1 + c4 * 4);
            Vs[row][c4] = *(const float4*)(vbase + (size_t)row * N1 + c4 * 4);
        }
        __syncthreads();

        float mnew = m;
        #pragma unroll 4
        for (int j = 0; j < 64; j++) {
            float dot = 0.f;
            #pragma unroll
            for (int i = 0; i < 16; i++) {
                float4 kk = Ks[j][i];
                dot += q[i].x * kk.x + q[i].y * kk.y
                     + q[i].z * kk.z + q[i].w * kk.w;
            }
            dot *= 0.125f;
            if (causal && (kt * 64 + j > r)) dot = -INFINITY;
            Sc[j][t] = dot;
            mnew = fmaxf(mnew, dot);
        }

        float scale = __expf(m - mnew);
        l *= scale;
        #pragma unroll
        for (int d = 0; d < 64; d++) o[d] *= scale;

        #pragma unroll 2
        for (int j = 0; j < 64; j++) {
            float p = __expf(Sc[j][t] - mnew);
            l += p;
            #pragma unroll
            for (int i = 0; i < 16; i++) {
                float4 vv = Vs[j][i];
                o[i * 4 + 0] += p * vv.x;
                o[i * 4 + 1] += p * vv.y;
                o[i * 4 + 2] += p * vv.z;
                o[i * 4 + 3] += p * vv.w;
            }
        }
        m = mnew;
        __syncthreads();
    }

    float inv = 1.f / l;
    float* obase = g_att + (size_t)(b * SS + r) * DD + h * DH;
    #pragma unroll
    for (int i = 0; i < 16; i++) {
        float4 ov = make_float4(tf32_rna(o[i * 4 + 0] * inv),
                                tf32_rna(o[i * 4 + 1] * inv),
                                tf32_rna(o[i * 4 + 2] * inv),
                                tf32_rna(o[i * 4 + 3] * inv));
        *(float4*)(obase + i * 4) = ov;
    }
}

// ---------------------------------------------------------------------------
extern "C" void kernel_launch(void* const* d_in, const int* in_sizes, int n_in,
                              void* d_out, int out_size)
{
    const float* x     = (const float*)d_in[0];
    const float* w_in  = (const float*)d_in[1];
    const float* b_in  = (const float*)d_in[2];
    const float* w_out = (const float*)d_in[3];
    const float* b_out = (const float*)d_in[4];
    const int*   cmask = (const int*)d_in[5];
    float* out = (float*)d_out;

    float *qkv, *att, *xr, *w1r, *w2r;
    cudaGetSymbolAddress((void**)&qkv, g_qkv);
    cudaGetSymbolAddress((void**)&att, g_att);
    cudaGetSymbolAddress((void**)&xr,  g_xr);
    cudaGetSymbolAddress((void**)&w1r, g_w1r);
    cudaGetSymbolAddress((void**)&w2r, g_w2r);

    cudaFuncSetAttribute(gemm_tf32mma,
                         cudaFuncAttributeMaxDynamicSharedMemorySize, GSMEM_BYTES);

    // 0) Round GEMM inputs to tf32-exact fp32
    {
        int n4x = MROWS * DD / 4, n41 = N1 * DD / 4, n42 = DD * DD / 4;
        round_tf32<<<(n4x + 255) / 256, 256>>>(x, xr, n4x);
        round_tf32<<<(n41 + 255) / 256, 256>>>(w_in, w1r, n41);
        round_tf32<<<(n42 + 255) / 256, 256>>>(w_out, w2r, n42);
    }

    // 1) QKV projection: [8192,1024] @ [3072,1024]^T + b_in
    gemm_tf32mma<<<dim3(N1 / 128, MROWS / 128), 256, GSMEM_BYTES>>>(
        xr, w1r, b_in, qkv, MROWS, N1, DD);

    // 2) Causal multi-head flash attention
    flash_attn<<<dim3(SS / 64, HH, BB), 64>>>(cmask);

    // 3) Output projection: [8192,1024] @ [1024,1024]^T + b_out
    gemm_tf32mma<<<dim3(DD / 128, MROWS / 128), 256, GSMEM_BYTES>>>(
        att, w2r, b_out, out, MROWS, DD, DD);
}

// round 4
// speedup vs baseline: 3.6669x; 2.2053x over previous
#include <cuda_runtime.h>
#include <math.h>
#include <stdint.h>

// Problem constants
#define BB 4
#define SS 2048
#define DD 1024
#define HH 16
#define DH 64
#define MROWS (BB * SS)      // 8192
#define N1 (3 * DD)          // 3072

// Scratch (allocation-free: device globals)
__device__ float g_qkv[(size_t)MROWS * N1];   // [B*S, 3D]
__device__ float g_att[(size_t)MROWS * DD];   // [B*S, D]  (tf32-rounded)
__device__ float g_xr [(size_t)MROWS * DD];   // x rounded to tf32
__device__ float g_w1r[(size_t)N1 * DD];      // w_in rounded
__device__ float g_w2r[(size_t)DD * DD];      // w_out rounded

// ===========================================================================
// helpers
// ===========================================================================
__device__ __forceinline__ uint32_t smem_u32(const void* p) {
    uint32_t a;
    asm("{ .reg .u64 t; cvta.to.shared.u64 t, %1; cvt.u32.u64 %0, t; }"
        : "=r"(a) : "l"(p));
    return a;
}
__device__ __forceinline__ float tf32_rna(float x) {
    uint32_t u;
    asm("cvt.rna.tf32.f32 %0, %1;" : "=r"(u) : "f"(x));
    return __uint_as_float(u);
}

#define MMA_TF32(acc, a0, a1, a2, a3, b0, b1) \
    asm volatile( \
        "mma.sync.aligned.m16n8k8.row.col.f32.tf32.tf32.f32 " \
        "{%0,%1,%2,%3}, {%4,%5,%6,%7}, {%8,%9}, {%0,%1,%2,%3};" \
        : "+f"((acc)[0]), "+f"((acc)[1]), "+f"((acc)[2]), "+f"((acc)[3]) \
        : "r"(a0), "r"(a1), "r"(a2), "r"(a3), "r"(b0), "r"(b1))

#define CP_A16(dst, src) \
    asm volatile("cp.async.cg.shared.global [%0], [%1], 16;" \
                 :: "r"(dst), "l"(src) : "memory")
#define CP_COMMIT() asm volatile("cp.async.commit_group;" ::: "memory")
#define CP_WAIT1()  asm volatile("cp.async.wait_group 1;" ::: "memory")
#define CP_WAIT0()  asm volatile("cp.async.wait_group 0;" ::: "memory")

// ===========================================================================
// tf32 rounding prep kernel (vectorized)
// ===========================================================================
__global__ void round_tf32(const float* __restrict__ s, float* __restrict__ d, int n4)
{
    int i = blockIdx.x * blockDim.x + threadIdx.x;
    if (i < n4) {
        float4 v = ((const float4*)s)[i];
        v.x = tf32_rna(v.x); v.y = tf32_rna(v.y);
        v.z = tf32_rna(v.z); v.w = tf32_rna(v.w);
        ((float4*)d)[i] = v;
    }
}

// ===========================================================================
// tf32 mma.sync GEMM: C[M,N] = A[M,K] @ B[N,K]^T + bias[N]
// CTA 128x128, BK=32, 3-stage cp.async, 8 warps (4 M x 2 N), warp tile 32x64.
// Inputs must already be tf32-exact fp32.
// ===========================================================================
#define STAGES  3
#define BKC     32
#define PAD_S   36
#define TILE_F  (128 * PAD_S)
#define STAGE_F (2 * TILE_F)
#define GSMEM_BYTES (STAGES * STAGE_F * 4)

__device__ __forceinline__ void compute_chunk(
    const float* __restrict__ As, const float* __restrict__ Bs,
    int wm, int wn, int g, int t, float acc[2][8][4])
{
    #pragma unroll
    for (int ks = 0; ks < 4; ks++) {
        const int kc = ks * 8;
        uint32_t af[2][4];
        #pragma unroll
        for (int mt = 0; mt < 2; mt++) {
            const float* ar = As + (wm * 32 + mt * 16 + g) * PAD_S + kc;
            af[mt][0] = __float_as_uint(ar[t]);
            af[mt][1] = __float_as_uint(ar[8 * PAD_S + t]);
            af[mt][2] = __float_as_uint(ar[t + 4]);
            af[mt][3] = __float_as_uint(ar[8 * PAD_S + t + 4]);
        }
        uint32_t bf[8][2];
        #pragma unroll
        for (int nt = 0; nt < 8; nt++) {
            const float* br = Bs + (wn * 64 + nt * 8 + g) * PAD_S + kc;
            bf[nt][0] = __float_as_uint(br[t]);
            bf[nt][1] = __float_as_uint(br[t + 4]);
        }
        #pragma unroll
        for (int mt = 0; mt < 2; mt++)
            #pragma unroll
            for (int nt = 0; nt < 8; nt++)
                MMA_TF32(acc[mt][nt], af[mt][0], af[mt][1], af[mt][2], af[mt][3],
                         bf[nt][0], bf[nt][1]);
    }
}

__global__ __launch_bounds__(256, 2) void gemm_tf32mma(
    const float* __restrict__ A, const float* __restrict__ Bm,
    const float* __restrict__ bias, float* __restrict__ C,
    int M, int N, int K)
{
    extern __shared__ float sm[];
    const uint32_t smb = smem_u32(sm);
    const int tid  = threadIdx.x;
    const int lane = tid & 31, wid = tid >> 5;
    const int g = lane >> 2, t = lane & 3;
    const int wm = wid & 3, wn = wid >> 2;
    const int bm = blockIdx.y * 128, bn = blockIdx.x * 128;

    const int lrow = tid >> 3;
    const int lc4  = tid & 7;
    const float* a0 = A + (size_t)(bm + lrow) * K + lc4 * 4;
    const float* a1 = a0 + (size_t)32 * K;
    const float* a2 = a0 + (size_t)64 * K;
    const float* a3 = a0 + (size_t)96 * K;
    const ptrdiff_t ab = (Bm + (size_t)(bn + lrow) * K + lc4 * 4) - a0;

    const uint32_t dA = smb + (uint32_t)((lrow * PAD_S + lc4 * 4) * 4);

    float acc[2][8][4];
    #pragma unroll
    for (int mt = 0; mt < 2; mt++)
        #pragma unroll
        for (int nt = 0; nt < 8; nt++)
            #pragma unroll
            for (int r = 0; r < 4; r++) acc[mt][nt][r] = 0.f;

#define ISSUE_CHUNK(c, s) do { \
    uint32_t _b = dA + (uint32_t)(s) * (STAGE_F * 4); \
    const float* _p0 = a0 + (c) * BKC; \
    const float* _p1 = a1 + (c) * BKC; \
    const float* _p2 = a2 + (c) * BKC; \
    const float* _p3 = a3 + (c) * BKC; \
    CP_A16(_b,                       _p0); \
    CP_A16(_b + 32 * PAD_S * 4,      _p1); \
    CP_A16(_b + 64 * PAD_S * 4,      _p2); \
    CP_A16(_b + 96 * PAD_S * 4,      _p3); \
    CP_A16(_b + TILE_F * 4,                  _p0 + ab); \
    CP_A16(_b + TILE_F * 4 + 32 * PAD_S * 4, _p1 + ab); \
    CP_A16(_b + TILE_F * 4 + 64 * PAD_S * 4, _p2 + ab); \
    CP_A16(_b + TILE_F * 4 + 96 * PAD_S * 4, _p3 + ab); \
    CP_COMMIT(); \
} while (0)

    const int NCH = K / BKC;
    ISSUE_CHUNK(0, 0);
    ISSUE_CHUNK(1, 1);

    for (int c = 0; c < NCH; c++) {
        if (c + 1 < NCH) { CP_WAIT1(); } else { CP_WAIT0(); }
        __syncthreads();
        if (c + 2 < NCH) ISSUE_CHUNK(c + 2, (c + 2) % STAGES);
        const float* As = sm + (c % STAGES) * STAGE_F;
        compute_chunk(As, As + TILE_F, wm, wn, g, t, acc);
    }
#undef ISSUE_CHUNK

    const int col0 = bn + wn * 64;
    #pragma unroll
    for (int mt = 0; mt < 2; mt++) {
        #pragma unroll
        for (int h = 0; h < 2; h++) {
            int row = bm + wm * 32 + mt * 16 + g + h * 8;
            float* cp = C + (size_t)row * N + col0;
            #pragma unroll
            for (int nt = 0; nt < 8; nt++) {
                int cc = nt * 8 + t * 2;
                float2 bz = *(const float2*)(bias + col0 + cc);
                float2 v;
                v.x = acc[mt][nt][h * 2 + 0] + bz.x;
                v.y = acc[mt][nt][h * 2 + 1] + bz.y;
                *(float2*)(cp + cc) = v;
            }
        }
    }
}

// ===========================================================================
// Tensor-core flash attention: block = (64-row q-tile, head, batch), 4 warps.
// Warp w owns rows w*16..w*16+15 completely (softmax stats intra-warp only).
// S = Q K^T and O += P V both via mma.sync tf32. V staged transposed.
// ===========================================================================
#define AST 68   // smem row stride (floats); 68 mod 32 == 4 -> conflict-free frags
#define ASMEM_BYTES (3 * 64 * AST * 4)   // Ks + Vt + Ps = 52224

__global__ __launch_bounds__(128) void flash_attn_tc(const int* __restrict__ causal_flag)
{
    extern __shared__ float smf[];
    float* Ks = smf;                 // [key][d]
    float* Vt = smf + 64 * AST;      // [d][key]
    float* Ps = smf + 2 * 64 * AST;  // Q staging, then P per-warp regions

    const int qt = blockIdx.x, h = blockIdx.y, b = blockIdx.z;
    const int tid = threadIdx.x, lane = tid & 31, w = tid >> 5;
    const int g = lane >> 2, t = lane & 3;
    const int causal = *causal_flag;
    const int r0 = w * 16 + g, r1 = r0 + 8;   // local row indices (0..63)

    // ---- stage Q (x 1/sqrt(DH), tf32-rounded) then extract A-fragments ----
    {
        const float* qb = g_qkv + (size_t)(b * SS + qt * 64) * N1 + h * DH;
        #pragma unroll
        for (int i = 0; i < 8; i++) {
            int fid = tid + i * 128, row = fid >> 4, c4 = fid & 15;
            float4 v = *(const float4*)(qb + (size_t)row * N1 + c4 * 4);
            float* d = Ps + row * AST + c4 * 4;
            d[0] = tf32_rna(v.x * 0.125f); d[1] = tf32_rna(v.y * 0.125f);
            d[2] = tf32_rna(v.z * 0.125f); d[3] = tf32_rna(v.w * 0.125f);
        }
    }
    __syncthreads();
    uint32_t qf[8][4];
    #pragma unroll
    for (int ks = 0; ks < 8; ks++) {
        const float* ar = Ps + r0 * AST + ks * 8;
        qf[ks][0] = __float_as_uint(ar[t]);
        qf[ks][1] = __float_as_uint(ar[8 * AST + t]);
        qf[ks][2] = __float_as_uint(ar[t + 4]);
        qf[ks][3] = __float_as_uint(ar[8 * AST + t + 4]);
    }

    float m0 = -INFINITY, m1 = -INFINITY, l0 = 0.f, l1 = 0.f;
    float oa[8][4];
    #pragma unroll
    for (int nt = 0; nt < 8; nt++)
        #pragma unroll
        for (int r = 0; r < 4; r++) oa[nt][r] = 0.f;

    const int ktmax = causal ? qt : (SS / 64 - 1);
    for (int kt = 0; kt <= ktmax; kt++) {
        __syncthreads();   // previous iter's MMA reads of Ks/Vt done
        // ---- load K tile (rounded) + V tile (rounded, transposed) ----
        const float* kb = g_qkv + (size_t)(b * SS + kt * 64) * N1 + DD + h * DH;
        const float* vb = kb + DD;
        #pragma unroll
        for (int i = 0; i < 8; i++) {
            int fid = tid + i * 128, row = fid >> 4, c4 = fid & 15;
            float4 kv = *(const float4*)(kb + (size_t)row * N1 + c4 * 4);
            float* kd = Ks + row * AST + c4 * 4;
            kd[0] = tf32_rna(kv.x); kd[1] = tf32_rna(kv.y);
            kd[2] = tf32_rna(kv.z); kd[3] = tf32_rna(kv.w);
            float4 vv = *(const float4*)(vb + (size_t)row * N1 + c4 * 4);
            Vt[(c4 * 4 + 0) * AST + row] = tf32_rna(vv.x);
            Vt[(c4 * 4 + 1) * AST + row] = tf32_rna(vv.y);
            Vt[(c4 * 4 + 2) * AST + row] = tf32_rna(vv.z);
            Vt[(c4 * 4 + 3) * AST + row] = tf32_rna(vv.w);
        }
        __syncthreads();

        // ---- S = Q K^T ----
        float sc[8][4];
        #pragma unroll
        for (int nt = 0; nt < 8; nt++)
            #pragma unroll
            for (int r = 0; r < 4; r++) sc[nt][r] = 0.f;
        #pragma unroll
        for (int ks = 0; ks < 8; ks++) {
            #pragma unroll
            for (int nt = 0; nt < 8; nt++) {
                const float* br = Ks + (nt * 8 + g) * AST + ks * 8;
                uint32_t b0 = __float_as_uint(br[t]);
                uint32_t b1 = __float_as_uint(br[t + 4]);
                MMA_TF32(sc[nt], qf[ks][0], qf[ks][1], qf[ks][2], qf[ks][3], b0, b1);
            }
        }

        // ---- causal mask on diagonal tile ----
        if (causal && kt == qt) {
            #pragma unroll
            for (int nt = 0; nt < 8; nt++) {
                int c0 = nt * 8 + 2 * t, c1 = c0 + 1;
                if (c0 > r0) sc[nt][0] = -INFINITY;
                if (c1 > r0) sc[nt][1] = -INFINITY;
                if (c0 > r1) sc[nt][2] = -INFINITY;
                if (c1 > r1) sc[nt][3] = -INFINITY;
            }
        }

        // ---- online softmax (per-row, quad shuffle reduce) ----
        float mx0 = m0, mx1 = m1;
        #pragma unroll
        for (int nt = 0; nt < 8; nt++) {
            mx0 = fmaxf(mx0, fmaxf(sc[nt][0], sc[nt][1]));
            mx1 = fmaxf(mx1, fmaxf(sc[nt][2], sc[nt][3]));
        }
        mx0 = fmaxf(mx0, __shfl_xor_sync(0xffffffffu, mx0, 1));
        mx0 = fmaxf(mx0, __shfl_xor_sync(0xffffffffu, mx0, 2));
        mx1 = fmaxf(mx1, __shfl_xor_sync(0xffffffffu, mx1, 1));
        mx1 = fmaxf(mx1, __shfl_xor_sync(0xffffffffu, mx1, 2));
        float a0 = __expf(m0 - mx0), a1 = __expf(m1 - mx1);
        m0 = mx0; m1 = mx1;
        l0 *= a0; l1 *= a1;

        float s0 = 0.f, s1 = 0.f;
        #pragma unroll
        for (int nt = 0; nt < 8; nt++) {
            float p00 = __expf(sc[nt][0] - m0);
            float p01 = __expf(sc[nt][1] - m0);
            float p10 = __expf(sc[nt][2] - m1);
            float p11 = __expf(sc[nt][3] - m1);
            s0 += p00 + p01; s1 += p10 + p11;
            *(float2*)(Ps + r0 * AST + nt * 8 + 2 * t) =
                make_float2(tf32_rna(p00), tf32_rna(p01));
            *(float2*)(Ps + r1 * AST + nt * 8 + 2 * t) =
                make_float2(tf32_rna(p10), tf32_rna(p11));
            oa[nt][0] *= a0; oa[nt][1] *= a0;
            oa[nt][2] *= a1; oa[nt][3] *= a1;
        }
        s0 += __shfl_xor_sync(0xffffffffu, s0, 1);
        s0 += __shfl_xor_sync(0xffffffffu, s0, 2);
        s1 += __shfl_xor_sync(0xffffffffu, s1, 1);
        s1 += __shfl_xor_sync(0xffffffffu, s1, 2);
        l0 += s0; l1 += s1;
        __syncwarp();   // P stores visible to A-fragment reads (cross-lane, same warp)

        // ---- O += P V ----
        #pragma unroll
        for (int ks = 0; ks < 8; ks++) {
            const float* ar = Ps + r0 * AST + ks * 8;
            uint32_t pa0 = __float_as_uint(ar[t]);
            uint32_t pa1 = __float_as_uint(ar[8 * AST + t]);
            uint32_t pa2 = __float_as_uint(ar[t + 4]);
            uint32_t pa3 = __float_as_uint(ar[8 * AST + t + 4]);
            #pragma unroll
            for (int nt = 0; nt < 8; nt++) {
                const float* br = Vt + (nt * 8 + g) * AST + ks * 8;
                uint32_t b0 = __float_as_uint(br[t]);
                uint32_t b1 = __float_as_uint(br[t + 4]);
                MMA_TF32(oa[nt], pa0, pa1, pa2, pa3, b0, b1);
            }
        }
        __syncwarp();
    }

    // ---- epilogue: normalize, round to tf32 (GEMM3 input), store ----
    float i0 = 1.f / l0, i1 = 1.f / l1;
    float* ob = g_att + (size_t)(b * SS + qt * 64) * DD + h * DH;
    #pragma unroll
    for (int nt = 0; nt < 8; nt++) {
        *(float2*)(ob + (size_t)r0 * DD + nt * 8 + 2 * t) =
            make_float2(tf32_rna(oa[nt][0] * i0), tf32_rna(oa[nt][1] * i0));
        *(float2*)(ob + (size_t)r1 * DD + nt * 8 + 2 * t) =
            make_float2(tf32_rna(oa[nt][2] * i1), tf32_rna(oa[nt][3] * i1));
    }
}

// ---------------------------------------------------------------------------
extern "C" void kernel_launch(void* const* d_in, const int* in_sizes, int n_in,
                              void* d_out, int out_size)
{
    const float* x     = (const float*)d_in[0];
    const float* w_in  = (const float*)d_in[1];
    const float* b_in  = (const float*)d_in[2];
    const float* w_out = (const float*)d_in[3];
    const float* b_out = (const float*)d_in[4];
    const int*   cmask = (const int*)d_in[5];
    float* out = (float*)d_out;

    float *qkv, *att, *xr, *w1r, *w2r;
    cudaGetSymbolAddress((void**)&qkv, g_qkv);
    cudaGetSymbolAddress((void**)&att, g_att);
    cudaGetSymbolAddress((void**)&xr,  g_xr);
    cudaGetSymbolAddress((void**)&w1r, g_w1r);
    cudaGetSymbolAddress((void**)&w2r, g_w2r);

    cudaFuncSetAttribute(gemm_tf32mma,
                         cudaFuncAttributeMaxDynamicSharedMemorySize, GSMEM_BYTES);
    cudaFuncSetAttribute(flash_attn_tc,
                         cudaFuncAttributeMaxDynamicSharedMemorySize, ASMEM_BYTES);

    // 0) Round GEMM inputs to tf32-exact fp32
    {
        int n4x = MROWS * DD / 4, n41 = N1 * DD / 4, n42 = DD * DD / 4;
        round_tf32<<<(n4x + 255) / 256, 256>>>(x, xr, n4x);
        round_tf32<<<(n41 + 255) / 256, 256>>>(w_in, w1r, n41);
        round_tf32<<<(n42 + 255) / 256, 256>>>(w_out, w2r, n42);
    }

    // 1) QKV projection: [8192,1024] @ [3072,1024]^T + b_in
    gemm_tf32mma<<<dim3(N1 / 128, MROWS / 128), 256, GSMEM_BYTES>>>(
        xr, w1r, b_in, qkv, MROWS, N1, DD);

    // 2) Causal multi-head flash attention (tensor cores)
    flash_attn_tc<<<dim3(SS / 64, HH, BB), 128, ASMEM_BYTES>>>(cmask);

    // 3) Output projection: [8192,1024] @ [1024,1024]^T + b_out
    gemm_tf32mma<<<dim3(DD / 128, MROWS / 128), 256, GSMEM_BYTES>>>(
        att, w2r, b_out, out, MROWS, DD, DD);
}

// round 5
// speedup vs baseline: 4.3721x; 1.1923x over previous
#include <cuda_runtime.h>
#include <math.h>
#include <stdint.h>

// Problem constants
#define BB 4
#define SS 2048
#define DD 1024
#define HH 16
#define DH 64
#define MROWS (BB * SS)      // 8192
#define N1 (3 * DD)          // 3072

// Scratch (allocation-free: device globals)
__device__ float g_qkv[(size_t)MROWS * N1];   // [B*S, 3D] tf32-rounded
__device__ float g_att[(size_t)MROWS * DD];   // [B*S, D]  tf32-rounded
__device__ float g_xr [(size_t)MROWS * DD];
__device__ float g_w1r[(size_t)N1 * DD];
__device__ float g_w2r[(size_t)DD * DD];

// ===========================================================================
// helpers
// ===========================================================================
__device__ __forceinline__ uint32_t smem_u32(const void* p) {
    uint32_t a;
    asm("{ .reg .u64 t; cvta.to.shared.u64 t, %1; cvt.u32.u64 %0, t; }"
        : "=r"(a) : "l"(p));
    return a;
}
__device__ __forceinline__ float tf32_rna(float x) {
    uint32_t u;
    asm("cvt.rna.tf32.f32 %0, %1;" : "=r"(u) : "f"(x));
    return __uint_as_float(u);
}

#define MMA_TF32(acc, a0, a1, a2, a3, b0, b1) \
    asm volatile( \
        "mma.sync.aligned.m16n8k8.row.col.f32.tf32.tf32.f32 " \
        "{%0,%1,%2,%3}, {%4,%5,%6,%7}, {%8,%9}, {%0,%1,%2,%3};" \
        : "+f"((acc)[0]), "+f"((acc)[1]), "+f"((acc)[2]), "+f"((acc)[3]) \
        : "r"(a0), "r"(a1), "r"(a2), "r"(a3), "r"(b0), "r"(b1))

#define CP_A16(dst, src) \
    asm volatile("cp.async.cg.shared.global [%0], [%1], 16;" \
                 :: "r"(dst), "l"(src) : "memory")
#define CP_COMMIT() asm volatile("cp.async.commit_group;" ::: "memory")
#define CP_WAIT1()  asm volatile("cp.async.wait_group 1;" ::: "memory")
#define CP_WAIT0()  asm volatile("cp.async.wait_group 0;" ::: "memory")

// ===========================================================================
// fused tf32 rounding prep (one launch for x, w_in, w_out)
// ===========================================================================
__global__ void round3_tf32(const float* __restrict__ x,  float* __restrict__ xr,
                            const float* __restrict__ w1, float* __restrict__ w1r,
                            const float* __restrict__ w2, float* __restrict__ w2r)
{
    const int nx = MROWS * DD / 4, n1 = N1 * DD / 4, n2 = DD * DD / 4;
    int i = blockIdx.x * blockDim.x + threadIdx.x;
    const float4* s; float4* d; int j;
    if (i < nx)            { s = (const float4*)x;  d = (float4*)xr;  j = i; }
    else if (i < nx + n1)  { s = (const float4*)w1; d = (float4*)w1r; j = i - nx; }
    else if (i < nx + n1 + n2) { s = (const float4*)w2; d = (float4*)w2r; j = i - nx - n1; }
    else return;
    float4 v = s[j];
    v.x = tf32_rna(v.x); v.y = tf32_rna(v.y);
    v.z = tf32_rna(v.z); v.w = tf32_rna(v.w);
    d[j] = v;
}

// ===========================================================================
// tf32 mma.sync GEMM: C[M,N] = A[M,K] @ B[N,K]^T + bias[N]
// CTA 128x128, BK=32, 3-stage cp.async, 4 warps (2x2), warp tile 64x64.
// ROUND_OUT: round outputs to tf32-exact fp32 (feeds next tf32 GEMM stage).
// ===========================================================================
#define STAGES  3
#define BKC     32
#define PAD_S   36
#define TILE_F  (128 * PAD_S)
#define STAGE_F (2 * TILE_F)
#define GSMEM_BYTES (STAGES * STAGE_F * 4)

template<int ROUND_OUT>
__global__ __launch_bounds__(128, 2) void gemm_tf32mma(
    const float* __restrict__ A, const float* __restrict__ Bm,
    const float* __restrict__ bias, float* __restrict__ C,
    int M, int N, int K)
{
    extern __shared__ float sm[];
    const uint32_t smb = smem_u32(sm);
    const int tid  = threadIdx.x;
    const int lane = tid & 31, wid = tid >> 5;
    const int g = lane >> 2, t = lane & 3;
    const int wm = wid & 1, wn = wid >> 1;
    const int bm = blockIdx.y * 128, bn = blockIdx.x * 128;

    const int lrow = tid >> 3;      // 0..15
    const int lc4  = tid & 7;
    const float* aBase = A  + (size_t)(bm + lrow) * K + lc4 * 4;
    const float* bBase = Bm + (size_t)(bn + lrow) * K + lc4 * 4;
    const uint32_t dA = smb + (uint32_t)((lrow * PAD_S + lc4 * 4) * 4);

    float acc[4][8][4];
    #pragma unroll
    for (int mt = 0; mt < 4; mt++)
        #pragma unroll
        for (int nt = 0; nt < 8; nt++)
            #pragma unroll
            for (int r = 0; r < 4; r++) acc[mt][nt][r] = 0.f;

#define ISSUE_CHUNK(c, s) do { \
    uint32_t _b = dA + (uint32_t)(s) * (STAGE_F * 4); \
    const float* _pa = aBase + (c) * BKC; \
    const float* _pb = bBase + (c) * BKC; \
    _Pragma("unroll") \
    for (int _i = 0; _i < 8; _i++) { \
        CP_A16(_b + _i * (16 * PAD_S * 4),              _pa + (size_t)_i * 16 * K); \
        CP_A16(_b + TILE_F * 4 + _i * (16 * PAD_S * 4), _pb + (size_t)_i * 16 * K); \
    } \
    CP_COMMIT(); \
} while (0)

    const int NCH = K / BKC;
    ISSUE_CHUNK(0, 0);
    ISSUE_CHUNK(1, 1);

    for (int c = 0; c < NCH; c++) {
        if (c + 1 < NCH) { CP_WAIT1(); } else { CP_WAIT0(); }
        __syncthreads();
        if (c + 2 < NCH) ISSUE_CHUNK(c + 2, (c + 2) % STAGES);
        const float* As = sm + (c % STAGES) * STAGE_F;
        const float* Bs = As + TILE_F;
        #pragma unroll
        for (int ks = 0; ks < 4; ks++) {
            const int kc = ks * 8;
            uint32_t af[4][4];
            #pragma unroll
            for (int mt = 0; mt < 4; mt++) {
                const float* ar = As + (wm * 64 + mt * 16 + g) * PAD_S + kc;
                af[mt][0] = __float_as_uint(ar[t]);
                af[mt][1] = __float_as_uint(ar[8 * PAD_S + t]);
                af[mt][2] = __float_as_uint(ar[t + 4]);
                af[mt][3] = __float_as_uint(ar[8 * PAD_S + t + 4]);
            }
            uint32_t bf[8][2];
            #pragma unroll
            for (int nt = 0; nt < 8; nt++) {
                const float* br = Bs + (wn * 64 + nt * 8 + g) * PAD_S + kc;
                bf[nt][0] = __float_as_uint(br[t]);
                bf[nt][1] = __float_as_uint(br[t + 4]);
            }
            #pragma unroll
            for (int mt = 0; mt < 4; mt++)
                #pragma unroll
                for (int nt = 0; nt < 8; nt++)
                    MMA_TF32(acc[mt][nt], af[mt][0], af[mt][1], af[mt][2], af[mt][3],
                             bf[nt][0], bf[nt][1]);
        }
    }
#undef ISSUE_CHUNK

    const int col0 = bn + wn * 64;
    #pragma unroll
    for (int mt = 0; mt < 4; mt++) {
        #pragma unroll
        for (int h = 0; h < 2; h++) {
            int row = bm + wm * 64 + mt * 16 + g + h * 8;
            float* cp = C + (size_t)row * N + col0;
            #pragma unroll
            for (int nt = 0; nt < 8; nt++) {
                int cc = nt * 8 + t * 2;
                float2 bz = *(const float2*)(bias + col0 + cc);
                float2 v;
                v.x = acc[mt][nt][h * 2 + 0] + bz.x;
                v.y = acc[mt][nt][h * 2 + 1] + bz.y;
                if (ROUND_OUT) { v.x = tf32_rna(v.x); v.y = tf32_rna(v.y); }
                *(float2*)(cp + cc) = v;
            }
        }
    }
}

// ===========================================================================
// Tensor-core flash attention. Block = (64-row q-tile, head, batch), 4 warps,
// warp owns 16 rows. K/V tiles cp.async double-buffered (inputs pre-rounded).
// V staged row-major [key][d] stride 72 (8t+g banks, conflict-free B-frags).
// ===========================================================================
#define KST 68
#define VST 72
#define AP_OFF  0                         // P / Q staging: 64 x KST
#define AK_OFF(s) (64 * KST * (1 + (s)))  // K buffers
#define AV_OFF(s) (64 * KST * 3 + (s) * 64 * VST)
#define ASMEM_BYTES ((64 * KST * 3 + 2 * 64 * VST) * 4)   // 89088

__global__ __launch_bounds__(128, 2) void flash_attn_tc(const int* __restrict__ causal_flag)
{
    extern __shared__ float smf[];
    const uint32_t sb = smem_u32(smf);
    float* Ps = smf + AP_OFF;

    const int qt = blockIdx.x, h = blockIdx.y, b = blockIdx.z;
    const int tid = threadIdx.x, lane = tid & 31, w = tid >> 5;
    const int g = lane >> 2, t = lane & 3;
    const int causal = *causal_flag;
    const int r0 = w * 16 + g, r1 = r0 + 8;

    const int ktmax = causal ? qt : (SS / 64 - 1);
    const float* kvb = g_qkv + (size_t)(b * SS) * N1 + DD + h * DH;
    const int irow = tid >> 4;     // 0..7 (+8i)
    const int ic4  = tid & 15;

#define ISSUE_KV(kt, s) do { \
    const float* _kb = kvb + (size_t)((kt) * 64) * N1; \
    uint32_t _kd = sb + (uint32_t)(AK_OFF(s) * 4); \
    uint32_t _vd = sb + (uint32_t)(AV_OFF(s) * 4); \
    _Pragma("unroll") \
    for (int _i = 0; _i < 8; _i++) { \
        int _r = irow + _i * 8; \
        const float* _src = _kb + (size_t)_r * N1 + ic4 * 4; \
        CP_A16(_kd + (uint32_t)((_r * KST + ic4 * 4) * 4), _src); \
        CP_A16(_vd + (uint32_t)((_r * VST + ic4 * 4) * 4), _src + DD); \
    } \
    CP_COMMIT(); \
} while (0)

    // prefetch tile 0 while staging Q
    ISSUE_KV(0, 0);

    // stage Q * 0.125 (exact scaling; g_qkv is pre-rounded)
    {
        const float* qb = g_qkv + (size_t)(b * SS + qt * 64) * N1 + h * DH;
        #pragma unroll
        for (int i = 0; i < 8; i++) {
            int fid = tid + i * 128, row = fid >> 4, c4 = fid & 15;
            float4 v = *(const float4*)(qb + (size_t)row * N1 + c4 * 4);
            float* d = Ps + row * KST + c4 * 4;
            d[0] = v.x * 0.125f; d[1] = v.y * 0.125f;
            d[2] = v.z * 0.125f; d[3] = v.w * 0.125f;
        }
    }
    __syncthreads();
    uint32_t qf[8][4];
    #pragma unroll
    for (int ks = 0; ks < 8; ks++) {
        const float* ar = Ps + r0 * KST + ks * 8;
        qf[ks][0] = __float_as_uint(ar[t]);
        qf[ks][1] = __float_as_uint(ar[8 * KST + t]);
        qf[ks][2] = __float_as_uint(ar[t + 4]);
        qf[ks][3] = __float_as_uint(ar[8 * KST + t + 4]);
    }

    float m0 = -INFINITY, m1 = -INFINITY, l0 = 0.f, l1 = 0.f;
    float oa[8][4];
    #pragma unroll
    for (int nt = 0; nt < 8; nt++)
        #pragma unroll
        for (int r = 0; r < 4; r++) oa[nt][r] = 0.f;

    for (int kt = 0; kt <= ktmax; kt++) {
        const int cur = kt & 1;
        CP_WAIT0();
        __syncthreads();   // tile kt landed; all compute on other buffer done
        if (kt < ktmax) ISSUE_KV(kt + 1, cur ^ 1);

        const float* Ks = smf + AK_OFF(cur);
        const float* Vs = smf + AV_OFF(cur);

        // ---- S = Q K^T ----
        float sc[8][4];
        #pragma unroll
        for (int nt = 0; nt < 8; nt++)
            #pragma unroll
            for (int r = 0; r < 4; r++) sc[nt][r] = 0.f;
        #pragma unroll
        for (int ks = 0; ks < 8; ks++) {
            #pragma unroll
            for (int nt = 0; nt < 8; nt++) {
                const float* br = Ks + (nt * 8 + g) * KST + ks * 8;
                uint32_t b0 = __float_as_uint(br[t]);
                uint32_t b1 = __float_as_uint(br[t + 4]);
                MMA_TF32(sc[nt], qf[ks][0], qf[ks][1], qf[ks][2], qf[ks][3], b0, b1);
            }
        }

        if (causal && kt == qt) {
            #pragma unroll
            for (int nt = 0; nt < 8; nt++) {
                int c0 = nt * 8 + 2 * t, c1 = c0 + 1;
                if (c0 > r0) sc[nt][0] = -INFINITY;
                if (c1 > r0) sc[nt][1] = -INFINITY;
                if (c0 > r1) sc[nt][2] = -INFINITY;
                if (c1 > r1) sc[nt][3] = -INFINITY;
            }
        }

        // ---- online softmax ----
        float mx0 = m0, mx1 = m1;
        #pragma unroll
        for (int nt = 0; nt < 8; nt++) {
            mx0 = fmaxf(mx0, fmaxf(sc[nt][0], sc[nt][1]));
            mx1 = fmaxf(mx1, fmaxf(sc[nt][2], sc[nt][3]));
        }
        mx0 = fmaxf(mx0, __shfl_xor_sync(0xffffffffu, mx0, 1));
        mx0 = fmaxf(mx0, __shfl_xor_sync(0xffffffffu, mx0, 2));
        mx1 = fmaxf(mx1, __shfl_xor_sync(0xffffffffu, mx1, 1));
        mx1 = fmaxf(mx1, __shfl_xor_sync(0xffffffffu, mx1, 2));
        float a0 = __expf(m0 - mx0), a1 = __expf(m1 - mx1);
        m0 = mx0; m1 = mx1;
        l0 *= a0; l1 *= a1;

        float s0 = 0.f, s1 = 0.f;
        #pragma unroll
        for (int nt = 0; nt < 8; nt++) {
            float p00 = __expf(sc[nt][0] - m0);
            float p01 = __expf(sc[nt][1] - m0);
            float p10 = __expf(sc[nt][2] - m1);
            float p11 = __expf(sc[nt][3] - m1);
            s0 += p00 + p01; s1 += p10 + p11;
            *(float2*)(Ps + r0 * KST + nt * 8 + 2 * t) =
                make_float2(tf32_rna(p00), tf32_rna(p01));
            *(float2*)(Ps + r1 * KST + nt * 8 + 2 * t) =
                make_float2(tf32_rna(p10), tf32_rna(p11));
            oa[nt][0] *= a0; oa[nt][1] *= a0;
            oa[nt][2] *= a1; oa[nt][3] *= a1;
        }
        s0 += __shfl_xor_sync(0xffffffffu, s0, 1);
        s0 += __shfl_xor_sync(0xffffffffu, s0, 2);
        s1 += __shfl_xor_sync(0xffffffffu, s1, 1);
        s1 += __shfl_xor_sync(0xffffffffu, s1, 2);
        l0 += s0; l1 += s1;
        __syncwarp();

        // ---- O += P V  (V row-major [key][d], stride VST) ----
        #pragma unroll
        for (int ks = 0; ks < 8; ks++) {
            const float* ar = Ps + r0 * KST + ks * 8;
            uint32_t pa0 = __float_as_uint(ar[t]);
            uint32_t pa1 = __float_as_uint(ar[8 * KST + t]);
            uint32_t pa2 = __float_as_uint(ar[t + 4]);
            uint32_t pa3 = __float_as_uint(ar[8 * KST + t + 4]);
            #pragma unroll
            for (int nt = 0; nt < 8; nt++) {
                uint32_t b0 = __float_as_uint(Vs[(ks * 8 + t) * VST + nt * 8 + g]);
                uint32_t b1 = __float_as_uint(Vs[(ks * 8 + t + 4) * VST + nt * 8 + g]);
                MMA_TF32(oa[nt], pa0, pa1, pa2, pa3, b0, b1);
            }
        }
        __syncwarp();
    }
#undef ISSUE_KV

    float i0 = 1.f / l0, i1 = 1.f / l1;
    float* ob = g_att + (size_t)(b * SS + qt * 64) * DD + h * DH;
    #pragma unroll
    for (int nt = 0; nt < 8; nt++) {
        *(float2*)(ob + (size_t)r0 * DD + nt * 8 + 2 * t) =
            make_float2(tf32_rna(oa[nt][0] * i0), tf32_rna(oa[nt][1] * i0));
        *(float2*)(ob + (size_t)r1 * DD + nt * 8 + 2 * t) =
            make_float2(tf32_rna(oa[nt][2] * i1), tf32_rna(oa[nt][3] * i1));
    }
}

// ---------------------------------------------------------------------------
extern "C" void kernel_launch(void* const* d_in, const int* in_sizes, int n_in,
                              void* d_out, int out_size)
{
    const float* x     = (const float*)d_in[0];
    const float* w_in  = (const float*)d_in[1];
    const float* b_in  = (const float*)d_in[2];
    const float* w_out = (const float*)d_in[3];
    const float* b_out = (const float*)d_in[4];
    const int*   cmask = (const int*)d_in[5];
    float* out = (float*)d_out;

    float *qkv, *att, *xr, *w1r, *w2r;
    cudaGetSymbolAddress((void**)&qkv, g_qkv);
    cudaGetSymbolAddress((void**)&att, g_att);
    cudaGetSymbolAddress((void**)&xr,  g_xr);
    cudaGetSymbolAddress((void**)&w1r, g_w1r);
    cudaGetSymbolAddress((void**)&w2r, g_w2r);

    cudaFuncSetAttribute(gemm_tf32mma<1>,
                         cudaFuncAttributeMaxDynamicSharedMemorySize, GSMEM_BYTES);
    cudaFuncSetAttribute(gemm_tf32mma<0>,
                         cudaFuncAttributeMaxDynamicSharedMemorySize, GSMEM_BYTES);
    cudaFuncSetAttribute(flash_attn_tc,
                         cudaFuncAttributeMaxDynamicSharedMemorySize, ASMEM_BYTES);

    // 0) round x, w_in, w_out to tf32-exact fp32 (one launch)
    {
        int tot = MROWS * DD / 4 + N1 * DD / 4 + DD * DD / 4;
        round3_tf32<<<(tot + 255) / 256, 256>>>(x, xr, w_in, w1r, w_out, w2r);
    }

    // 1) QKV projection (output rounded for the attention stage)
    gemm_tf32mma<1><<<dim3(N1 / 128, MROWS / 128), 128, GSMEM_BYTES>>>(
        xr, w1r, b_in, qkv, MROWS, N1, DD);

    // 2) Causal multi-head flash attention (tensor cores, cp.async pipelined)
    flash_attn_tc<<<dim3(SS / 64, HH, BB), 128, ASMEM_BYTES>>>(cmask);

    // 3) Output projection (plain fp32 output)
    gemm_tf32mma<0><<<dim3(DD / 128, MROWS / 128), 128, GSMEM_BYTES>>>(
        att, w2r, b_out, out, MROWS, DD, DD);
}

// round 6
// speedup vs baseline: 4.5499x; 1.0407x over previous
#include <cuda_runtime.h>
#include <math.h>
#include <stdint.h>

// Problem constants
#define BB 4
#define SS 2048
#define DD 1024
#define HH 16
#define DH 64
#define MROWS (BB * SS)      // 8192
#define N1 (3 * DD)          // 3072

// Scratch (allocation-free: device globals)
__device__ float g_qkv[(size_t)MROWS * N1];   // [B*S, 3D] tf32-rounded
__device__ float g_att[(size_t)MROWS * DD];   // [B*S, D]  tf32-rounded
__device__ float g_xr [(size_t)MROWS * DD];
__device__ float g_w1r[(size_t)N1 * DD];
__device__ float g_w2r[(size_t)DD * DD];

// ===========================================================================
// helpers
// ===========================================================================
__device__ __forceinline__ uint32_t smem_u32(const void* p) {
    uint32_t a;
    asm("{ .reg .u64 t; cvta.to.shared.u64 t, %1; cvt.u32.u64 %0, t; }"
        : "=r"(a) : "l"(p));
    return a;
}
__device__ __forceinline__ float tf32_rna(float x) {
    uint32_t u;
    asm("cvt.rna.tf32.f32 %0, %1;" : "=r"(u) : "f"(x));
    return __uint_as_float(u);
}

#define MMA_TF32(acc, a0, a1, a2, a3, b0, b1) \
    asm volatile( \
        "mma.sync.aligned.m16n8k8.row.col.f32.tf32.tf32.f32 " \
        "{%0,%1,%2,%3}, {%4,%5,%6,%7}, {%8,%9}, {%0,%1,%2,%3};" \
        : "+f"((acc)[0]), "+f"((acc)[1]), "+f"((acc)[2]), "+f"((acc)[3]) \
        : "r"(a0), "r"(a1), "r"(a2), "r"(a3), "r"(b0), "r"(b1))

#define LDSM4(r, a) \
    asm volatile("ldmatrix.sync.aligned.m8n8.x4.shared.b16 {%0,%1,%2,%3}, [%4];" \
        : "=r"((r)[0]), "=r"((r)[1]), "=r"((r)[2]), "=r"((r)[3]) : "r"(a))

#define CP_A16(dst, src) \
    asm volatile("cp.async.cg.shared.global [%0], [%1], 16;" \
                 :: "r"(dst), "l"(src) : "memory")
#define CP_COMMIT() asm volatile("cp.async.commit_group;" ::: "memory")
#define CP_WAIT1()  asm volatile("cp.async.wait_group 1;" ::: "memory")
#define CP_WAIT0()  asm volatile("cp.async.wait_group 0;" ::: "memory")

// ===========================================================================
// fused tf32 rounding prep (one launch for x, w_in, w_out)
// ===========================================================================
__global__ void round3_tf32(const float* __restrict__ x,  float* __restrict__ xr,
                            const float* __restrict__ w1, float* __restrict__ w1r,
                            const float* __restrict__ w2, float* __restrict__ w2r)
{
    const int nx = MROWS * DD / 4, n1 = N1 * DD / 4, n2 = DD * DD / 4;
    int i = blockIdx.x * blockDim.x + threadIdx.x;
    const float4* s; float4* d; int j;
    if (i < nx)            { s = (const float4*)x;  d = (float4*)xr;  j = i; }
    else if (i < nx + n1)  { s = (const float4*)w1; d = (float4*)w1r; j = i - nx; }
    else if (i < nx + n1 + n2) { s = (const float4*)w2; d = (float4*)w2r; j = i - nx - n1; }
    else return;
    float4 v = s[j];
    v.x = tf32_rna(v.x); v.y = tf32_rna(v.y);
    v.z = tf32_rna(v.z); v.w = tf32_rna(v.w);
    d[j] = v;
}

// ===========================================================================
// tf32 mma.sync GEMM: C[M,N] = A[M,K] @ B[N,K]^T + bias[N]
// CTA 128x128, BK=32, 3-stage cp.async, 8 warps (4Mx2N), warp tile 32x64.
// All fragment loads via ldmatrix.x4.
// ===========================================================================
#define STAGES  3
#define BKC     32
#define PAD_S   36
#define TILE_F  (128 * PAD_S)
#define STAGE_F (2 * TILE_F)
#define GSMEM_BYTES (STAGES * STAGE_F * 4)

template<int ROUND_OUT>
__global__ __launch_bounds__(256, 2) void gemm_tf32mma(
    const float* __restrict__ A, const float* __restrict__ Bm,
    const float* __restrict__ bias, float* __restrict__ C,
    int M, int N, int K)
{
    extern __shared__ float sm[];
    const uint32_t smb = smem_u32(sm);
    const int tid  = threadIdx.x;
    const int lane = tid & 31, wid = tid >> 5;
    const int g = lane >> 2, t = lane & 3;
    const int wm = wid & 3, wn = wid >> 2;
    const int bm = blockIdx.y * 128, bn = blockIdx.x * 128;

    // cp.async mapping: thread -> rows lrow+32i, float4-col lc4
    const int lrow = tid >> 3;
    const int lc4  = tid & 7;
    const float* aBase = A  + (size_t)(bm + lrow) * K + lc4 * 4;
    const float* bBase = Bm + (size_t)(bn + lrow) * K + lc4 * 4;
    const uint32_t dA = smb + (uint32_t)((lrow * PAD_S + lc4 * 4) * 4);

    // ldmatrix lane addresses (stage 0, ks 0)
    uint32_t aAddr0, bAddr0;
    {
        int ar = wm * 32 + (lane & 15);
        int ac = (lane >> 4) * 4;
        aAddr0 = smb + (uint32_t)((ar * PAD_S + ac) * 4);
        int br = wn * 64 + (lane & 7) + ((lane & 16) >> 1);
        int bc = (lane & 8) >> 1;
        bAddr0 = smb + (uint32_t)((TILE_F + br * PAD_S + bc) * 4);
    }

    float acc[2][8][4];
    #pragma unroll
    for (int mt = 0; mt < 2; mt++)
        #pragma unroll
        for (int nt = 0; nt < 8; nt++)
            #pragma unroll
            for (int r = 0; r < 4; r++) acc[mt][nt][r] = 0.f;

#define ISSUE_CHUNK(c, s) do { \
    uint32_t _b = dA + (uint32_t)(s) * (STAGE_F * 4); \
    const float* _pa = aBase + (c) * BKC; \
    const float* _pb = bBase + (c) * BKC; \
    _Pragma("unroll") \
    for (int _i = 0; _i < 4; _i++) { \
        CP_A16(_b + _i * (32 * PAD_S * 4),              _pa + (size_t)_i * 32 * K); \
        CP_A16(_b + TILE_F * 4 + _i * (32 * PAD_S * 4), _pb + (size_t)_i * 32 * K); \
    } \
    CP_COMMIT(); \
} while (0)

    const int NCH = K / BKC;
    ISSUE_CHUNK(0, 0);
    ISSUE_CHUNK(1, 1);

    for (int c = 0; c < NCH; c++) {
        if (c + 1 < NCH) { CP_WAIT1(); } else { CP_WAIT0(); }
        __syncthreads();
        if (c + 2 < NCH) ISSUE_CHUNK(c + 2, (c + 2) % STAGES);
        const uint32_t soff = (uint32_t)((c % STAGES) * (STAGE_F * 4));
        #pragma unroll
        for (int ks = 0; ks < 4; ks++) {
            const uint32_t koff = soff + ks * 32;   // ks*8 floats
            uint32_t af[2][4], bq[4][4];
            LDSM4(af[0], aAddr0 + koff);
            LDSM4(af[1], aAddr0 + koff + 16 * PAD_S * 4);
            #pragma unroll
            for (int p = 0; p < 4; p++)
                LDSM4(bq[p], bAddr0 + koff + p * (16 * PAD_S * 4));
            #pragma unroll
            for (int mt = 0; mt < 2; mt++)
                #pragma unroll
                for (int nt = 0; nt < 8; nt++)
                    MMA_TF32(acc[mt][nt],
                             af[mt][0], af[mt][1], af[mt][2], af[mt][3],
                             bq[nt >> 1][(nt & 1) * 2], bq[nt >> 1][(nt & 1) * 2 + 1]);
        }
    }
#undef ISSUE_CHUNK

    const int col0 = bn + wn * 64;
    #pragma unroll
    for (int mt = 0; mt < 2; mt++) {
        #pragma unroll
        for (int h = 0; h < 2; h++) {
            int row = bm + wm * 32 + mt * 16 + g + h * 8;
            float* cp = C + (size_t)row * N + col0;
            #pragma unroll
            for (int nt = 0; nt < 8; nt++) {
                int cc = nt * 8 + t * 2;
                float2 bz = *(const float2*)(bias + col0 + cc);
                float2 v;
                v.x = acc[mt][nt][h * 2 + 0] + bz.x;
                v.y = acc[mt][nt][h * 2 + 1] + bz.y;
                if (ROUND_OUT) { v.x = tf32_rna(v.x); v.y = tf32_rna(v.y); }
                *(float2*)(cp + cc) = v;
            }
        }
    }
}

// ===========================================================================
// Tensor-core flash attention. Block = (64-row q-tile, head, batch), 4 warps,
// warp owns 16 rows. K/V cp.async double-buffered; Q/K/P frags via ldmatrix.
// ===========================================================================
#define KST 68
#define VST 72
#define AP_OFF  0
#define AK_OFF(s) (64 * KST * (1 + (s)))
#define AV_OFF(s) (64 * KST * 3 + (s) * 64 * VST)
#define ASMEM_BYTES ((64 * KST * 3 + 2 * 64 * VST) * 4)   // 89088

__global__ __launch_bounds__(128, 2) void flash_attn_tc(const int* __restrict__ causal_flag)
{
    extern __shared__ float smf[];
    const uint32_t sb = smem_u32(smf);
    float* Ps = smf + AP_OFF;

    const int qt = blockIdx.x, h = blockIdx.y, b = blockIdx.z;
    const int tid = threadIdx.x, lane = tid & 31, w = tid >> 5;
    const int g = lane >> 2, t = lane & 3;
    const int causal = *causal_flag;
    const int r0 = w * 16 + g, r1 = r0 + 8;

    const int ktmax = causal ? qt : (SS / 64 - 1);
    const float* kvb = g_qkv + (size_t)(b * SS) * N1 + DD + h * DH;
    const int irow = tid >> 4;     // 0..7
    const int ic4  = tid & 15;

    // ldmatrix lane addresses
    const uint32_t pAddr = sb + (uint32_t)(((w * 16 + (lane & 15)) * KST
                                            + (lane >> 4) * 4) * 4);
    const uint32_t kAddr = sb + (uint32_t)((AK_OFF(0)
                         + ((lane & 7) + ((lane & 16) >> 1)) * KST
                         + ((lane & 8) >> 1)) * 4);

#define ISSUE_KV(kt, s) do { \
    const float* _kb = kvb + (size_t)((kt) * 64) * N1; \
    uint32_t _kd = sb + (uint32_t)(AK_OFF(s) * 4); \
    uint32_t _vd = sb + (uint32_t)(AV_OFF(s) * 4); \
    _Pragma("unroll") \
    for (int _i = 0; _i < 8; _i++) { \
        int _r = irow + _i * 8; \
        const float* _src = _kb + (size_t)_r * N1 + ic4 * 4; \
        CP_A16(_kd + (uint32_t)((_r * KST + ic4 * 4) * 4), _src); \
        CP_A16(_vd + (uint32_t)((_r * VST + ic4 * 4) * 4), _src + DD); \
    } \
    CP_COMMIT(); \
} while (0)

    ISSUE_KV(0, 0);

    // stage Q * 0.125 (exact; g_qkv pre-rounded)
    {
        const float* qb = g_qkv + (size_t)(b * SS + qt * 64) * N1 + h * DH;
        #pragma unroll
        for (int i = 0; i < 8; i++) {
            int fid = tid + i * 128, row = fid >> 4, c4 = fid & 15;
            float4 v = *(const float4*)(qb + (size_t)row * N1 + c4 * 4);
            float* d = Ps + row * KST + c4 * 4;
            d[0] = v.x * 0.125f; d[1] = v.y * 0.125f;
            d[2] = v.z * 0.125f; d[3] = v.w * 0.125f;
        }
    }
    __syncthreads();
    uint32_t qf[8][4];
    #pragma unroll
    for (int ks = 0; ks < 8; ks++) LDSM4(qf[ks], pAddr + ks * 32);

    float m0 = -INFINITY, m1 = -INFINITY, l0 = 0.f, l1 = 0.f;
    float oa[8][4];
    #pragma unroll
    for (int nt = 0; nt < 8; nt++)
        #pragma unroll
        for (int r = 0; r < 4; r++) oa[nt][r] = 0.f;

    for (int kt = 0; kt <= ktmax; kt++) {
        const int cur = kt & 1;
        CP_WAIT0();
        __syncthreads();
        if (kt < ktmax) ISSUE_KV(kt + 1, cur ^ 1);

        const float* Vs = smf + AV_OFF(cur);
        const uint32_t kOff = (uint32_t)(cur * (64 * KST * 4));

        // ---- S = Q K^T ----
        float sc[8][4];
        #pragma unroll
        for (int nt = 0; nt < 8; nt++)
            #pragma unroll
            for (int r = 0; r < 4; r++) sc[nt][r] = 0.f;
        #pragma unroll
        for (int ks = 0; ks < 8; ks++) {
            uint32_t kb[4][4];
            #pragma unroll
            for (int p = 0; p < 4; p++)
                LDSM4(kb[p], kAddr + kOff + ks * 32 + p * (16 * KST * 4));
            #pragma unroll
            for (int nt = 0; nt < 8; nt++)
                MMA_TF32(sc[nt], qf[ks][0], qf[ks][1], qf[ks][2], qf[ks][3],
                         kb[nt >> 1][(nt & 1) * 2], kb[nt >> 1][(nt & 1) * 2 + 1]);
        }

        if (causal && kt == qt) {
            #pragma unroll
            for (int nt = 0; nt < 8; nt++) {
                int c0 = nt * 8 + 2 * t, c1 = c0 + 1;
                if (c0 > r0) sc[nt][0] = -INFINITY;
                if (c1 > r0) sc[nt][1] = -INFINITY;
                if (c0 > r1) sc[nt][2] = -INFINITY;
                if (c1 > r1) sc[nt][3] = -INFINITY;
            }
        }

        // ---- online softmax ----
        float mx0 = m0, mx1 = m1;
        #pragma unroll
        for (int nt = 0; nt < 8; nt++) {
            mx0 = fmaxf(mx0, fmaxf(sc[nt][0], sc[nt][1]));
            mx1 = fmaxf(mx1, fmaxf(sc[nt][2], sc[nt][3]));
        }
        mx0 = fmaxf(mx0, __shfl_xor_sync(0xffffffffu, mx0, 1));
        mx0 = fmaxf(mx0, __shfl_xor_sync(0xffffffffu, mx0, 2));
        mx1 = fmaxf(mx1, __shfl_xor_sync(0xffffffffu, mx1, 1));
        mx1 = fmaxf(mx1, __shfl_xor_sync(0xffffffffu, mx1, 2));
        float a0 = __expf(m0 - mx0), a1 = __expf(m1 - mx1);
        m0 = mx0; m1 = mx1;
        l0 *= a0; l1 *= a1;

        float s0 = 0.f, s1 = 0.f;
        #pragma unroll
        for (int nt = 0; nt < 8; nt++) {
            float p00 = __expf(sc[nt][0] - m0);
            float p01 = __expf(sc[nt][1] - m0);
            float p10 = __expf(sc[nt][2] - m1);
            float p11 = __expf(sc[nt][3] - m1);
            s0 += p00 + p01; s1 += p10 + p11;
            *(float2*)(Ps + r0 * KST + nt * 8 + 2 * t) =
                make_float2(tf32_rna(p00), tf32_rna(p01));
            *(float2*)(Ps + r1 * KST + nt * 8 + 2 * t) =
                make_float2(tf32_rna(p10), tf32_rna(p11));
            oa[nt][0] *= a0; oa[nt][1] *= a0;
            oa[nt][2] *= a1; oa[nt][3] *= a1;
        }
        s0 += __shfl_xor_sync(0xffffffffu, s0, 1);
        s0 += __shfl_xor_sync(0xffffffffu, s0, 2);
        s1 += __shfl_xor_sync(0xffffffffu, s1, 1);
        s1 += __shfl_xor_sync(0xffffffffu, s1, 2);
        l0 += s0; l1 += s1;
        __syncwarp();

        // ---- O += P V  (V row-major [key][d], stride VST) ----
        #pragma unroll
        for (int ks = 0; ks < 8; ks++) {
            uint32_t pf[4];
            LDSM4(pf, pAddr + ks * 32);
            #pragma unroll
            for (int nt = 0; nt < 8; nt++) {
                uint32_t b0 = __float_as_uint(Vs[(ks * 8 + t) * VST + nt * 8 + g]);
                uint32_t b1 = __float_as_uint(Vs[(ks * 8 + t + 4) * VST + nt * 8 + g]);
                MMA_TF32(oa[nt], pf[0], pf[1], pf[2], pf[3], b0, b1);
            }
        }
        __syncwarp();
    }
#undef ISSUE_KV

    float i0 = 1.f / l0, i1 = 1.f / l1;
    float* ob = g_att + (size_t)(b * SS + qt * 64) * DD + h * DH;
    #pragma unroll
    for (int nt = 0; nt < 8; nt++) {
        *(float2*)(ob + (size_t)r0 * DD + nt * 8 + 2 * t) =
            make_float2(tf32_rna(oa[nt][0] * i0), tf32_rna(oa[nt][1] * i0));
        *(float2*)(ob + (size_t)r1 * DD + nt * 8 + 2 * t) =
            make_float2(tf32_rna(oa[nt][2] * i1), tf32_rna(oa[nt][3] * i1));
    }
}

// ---------------------------------------------------------------------------
extern "C" void kernel_launch(void* const* d_in, const int* in_sizes, int n_in,
                              void* d_out, int out_size)
{
    const float* x     = (const float*)d_in[0];
    const float* w_in  = (const float*)d_in[1];
    const float* b_in  = (const float*)d_in[2];
    const float* w_out = (const float*)d_in[3];
    const float* b_out = (const float*)d_in[4];
    const int*   cmask = (const int*)d_in[5];
    float* out = (float*)d_out;

    float *qkv, *att, *xr, *w1r, *w2r;
    cudaGetSymbolAddress((void**)&qkv, g_qkv);
    cudaGetSymbolAddress((void**)&att, g_att);
    cudaGetSymbolAddress((void**)&xr,  g_xr);
    cudaGetSymbolAddress((void**)&w1r, g_w1r);
    cudaGetSymbolAddress((void**)&w2r, g_w2r);

    cudaFuncSetAttribute(gemm_tf32mma<1>,
                         cudaFuncAttributeMaxDynamicSharedMemorySize, GSMEM_BYTES);
    cudaFuncSetAttribute(gemm_tf32mma<0>,
                         cudaFuncAttributeMaxDynamicSharedMemorySize, GSMEM_BYTES);
    cudaFuncSetAttribute(flash_attn_tc,
                         cudaFuncAttributeMaxDynamicSharedMemorySize, ASMEM_BYTES);

    // 0) round x, w_in, w_out to tf32-exact fp32 (one launch)
    {
        int tot = MROWS * DD / 4 + N1 * DD / 4 + DD * DD / 4;
        round3_tf32<<<(tot + 255) / 256, 256>>>(x, xr, w_in, w1r, w_out, w2r);
    }

    // 1) QKV projection (output rounded for the attention stage)
    gemm_tf32mma<1><<<dim3(N1 / 128, MROWS / 128), 256, GSMEM_BYTES>>>(
        xr, w1r, b_in, qkv, MROWS, N1, DD);

    // 2) Causal multi-head flash attention (tensor cores, cp.async pipelined)
    flash_attn_tc<<<dim3(SS / 64, HH, BB), 128, ASMEM_BYTES>>>(cmask);

    // 3) Output projection (plain fp32 output)
    gemm_tf32mma<0><<<dim3(DD / 128, MROWS / 128), 256, GSMEM_BYTES>>>(
        att, w2r, b_out, out, MROWS, DD, DD);
}

// round 7
// speedup vs baseline: 4.6858x; 1.0299x over previous
#include <cuda_runtime.h>
#include <math.h>
#include <stdint.h>

// Problem constants
#define BB 4
#define SS 2048
#define DD 1024
#define HH 16
#define DH 64
#define MROWS (BB * SS)      // 8192
#define N1 (3 * DD)          // 3072

// Scratch (allocation-free: device globals)
__device__ float g_qkv[(size_t)MROWS * N1];   // [B*S, 3D] tf32-rounded
__device__ float g_att[(size_t)MROWS * DD];   // [B*S, D]  tf32-rounded
__device__ float g_xr [(size_t)MROWS * DD];
__device__ float g_w1r[(size_t)N1 * DD];
__device__ float g_w2r[(size_t)DD * DD];

// ===========================================================================
// helpers
// ===========================================================================
__device__ __forceinline__ uint32_t smem_u32(const void* p) {
    uint32_t a;
    asm("{ .reg .u64 t; cvta.to.shared.u64 t, %1; cvt.u32.u64 %0, t; }"
        : "=r"(a) : "l"(p));
    return a;
}
__device__ __forceinline__ float tf32_rna(float x) {
    uint32_t u;
    asm("cvt.rna.tf32.f32 %0, %1;" : "=r"(u) : "f"(x));
    return __uint_as_float(u);
}

#define MMA_TF32(acc, a0, a1, a2, a3, b0, b1) \
    asm volatile( \
        "mma.sync.aligned.m16n8k8.row.col.f32.tf32.tf32.f32 " \
        "{%0,%1,%2,%3}, {%4,%5,%6,%7}, {%8,%9}, {%0,%1,%2,%3};" \
        : "+f"((acc)[0]), "+f"((acc)[1]), "+f"((acc)[2]), "+f"((acc)[3]) \
        : "r"(a0), "r"(a1), "r"(a2), "r"(a3), "r"(b0), "r"(b1))

#define LDSM4(r, a) \
    asm volatile("ldmatrix.sync.aligned.m8n8.x4.shared.b16 {%0,%1,%2,%3}, [%4];" \
        : "=r"((r)[0]), "=r"((r)[1]), "=r"((r)[2]), "=r"((r)[3]) : "r"(a))

#define CP_A16(dst, src) \
    asm volatile("cp.async.cg.shared.global [%0], [%1], 16;" \
                 :: "r"(dst), "l"(src) : "memory")
#define CP_COMMIT() asm volatile("cp.async.commit_group;" ::: "memory")
#define CP_WAIT1()  asm volatile("cp.async.wait_group 1;" ::: "memory")
#define CP_WAIT0()  asm volatile("cp.async.wait_group 0;" ::: "memory")

// ===========================================================================
// fused tf32 rounding prep (one launch for x, w_in, w_out)
// ===========================================================================
__global__ void round3_tf32(const float* __restrict__ x,  float* __restrict__ xr,
                            const float* __restrict__ w1, float* __restrict__ w1r,
                            const float* __restrict__ w2, float* __restrict__ w2r)
{
    const int nx = MROWS * DD / 4, n1 = N1 * DD / 4, n2 = DD * DD / 4;
    int i = blockIdx.x * blockDim.x + threadIdx.x;
    const float4* s; float4* d; int j;
    if (i < nx)            { s = (const float4*)x;  d = (float4*)xr;  j = i; }
    else if (i < nx + n1)  { s = (const float4*)w1; d = (float4*)w1r; j = i - nx; }
    else if (i < nx + n1 + n2) { s = (const float4*)w2; d = (float4*)w2r; j = i - nx - n1; }
    else return;
    float4 v = s[j];
    v.x = tf32_rna(v.x); v.y = tf32_rna(v.y);
    v.z = tf32_rna(v.z); v.w = tf32_rna(v.w);
    d[j] = v;
}

// ===========================================================================
// tf32 mma.sync GEMM: C[M,N] = A[M,K] @ B[N,K]^T + bias[N]
// CTA 128x128, BK=32, 3-stage cp.async, 8 warps (4Mx2N), warp tile 32x64.
// ===========================================================================
#define STAGES  3
#define BKC     32
#define PAD_S   36
#define TILE_F  (128 * PAD_S)
#define STAGE_F (2 * TILE_F)
#define GSMEM_BYTES (STAGES * STAGE_F * 4)

template<int ROUND_OUT>
__global__ __launch_bounds__(256, 2) void gemm_tf32mma(
    const float* __restrict__ A, const float* __restrict__ Bm,
    const float* __restrict__ bias, float* __restrict__ C,
    int M, int N, int K)
{
    extern __shared__ float sm[];
    const uint32_t smb = smem_u32(sm);
    const int tid  = threadIdx.x;
    const int lane = tid & 31, wid = tid >> 5;
    const int g = lane >> 2, t = lane & 3;
    const int wm = wid & 3, wn = wid >> 2;
    const int bm = blockIdx.y * 128, bn = blockIdx.x * 128;

    const int lrow = tid >> 3;
    const int lc4  = tid & 7;
    const float* aBase = A  + (size_t)(bm + lrow) * K + lc4 * 4;
    const float* bBase = Bm + (size_t)(bn + lrow) * K + lc4 * 4;
    const uint32_t dA = smb + (uint32_t)((lrow * PAD_S + lc4 * 4) * 4);

    uint32_t aAddr0, bAddr0;
    {
        int ar = wm * 32 + (lane & 15);
        int ac = (lane >> 4) * 4;
        aAddr0 = smb + (uint32_t)((ar * PAD_S + ac) * 4);
        int br = wn * 64 + (lane & 7) + ((lane & 16) >> 1);
        int bc = (lane & 8) >> 1;
        bAddr0 = smb + (uint32_t)((TILE_F + br * PAD_S + bc) * 4);
    }

    float acc[2][8][4];
    #pragma unroll
    for (int mt = 0; mt < 2; mt++)
        #pragma unroll
        for (int nt = 0; nt < 8; nt++)
            #pragma unroll
            for (int r = 0; r < 4; r++) acc[mt][nt][r] = 0.f;

#define ISSUE_CHUNK(c, s) do { \
    uint32_t _b = dA + (uint32_t)(s) * (STAGE_F * 4); \
    const float* _pa = aBase + (c) * BKC; \
    const float* _pb = bBase + (c) * BKC; \
    _Pragma("unroll") \
    for (int _i = 0; _i < 4; _i++) { \
        CP_A16(_b + _i * (32 * PAD_S * 4),              _pa + (size_t)_i * 32 * K); \
        CP_A16(_b + TILE_F * 4 + _i * (32 * PAD_S * 4), _pb + (size_t)_i * 32 * K); \
    } \
    CP_COMMIT(); \
} while (0)

    const int NCH = K / BKC;
    ISSUE_CHUNK(0, 0);
    ISSUE_CHUNK(1, 1);

    for (int c = 0; c < NCH; c++) {
        if (c + 1 < NCH) { CP_WAIT1(); } else { CP_WAIT0(); }
        __syncthreads();
        if (c + 2 < NCH) ISSUE_CHUNK(c + 2, (c + 2) % STAGES);
        const uint32_t soff = (uint32_t)((c % STAGES) * (STAGE_F * 4));
        #pragma unroll
        for (int ks = 0; ks < 4; ks++) {
            const uint32_t koff = soff + ks * 32;
            uint32_t af[2][4], bq[4][4];
            LDSM4(af[0], aAddr0 + koff);
            LDSM4(af[1], aAddr0 + koff + 16 * PAD_S * 4);
            #pragma unroll
            for (int p = 0; p < 4; p++)
                LDSM4(bq[p], bAddr0 + koff + p * (16 * PAD_S * 4));
            #pragma unroll
            for (int mt = 0; mt < 2; mt++)
                #pragma unroll
                for (int nt = 0; nt < 8; nt++)
                    MMA_TF32(acc[mt][nt],
                             af[mt][0], af[mt][1], af[mt][2], af[mt][3],
                             bq[nt >> 1][(nt & 1) * 2], bq[nt >> 1][(nt & 1) * 2 + 1]);
        }
    }
#undef ISSUE_CHUNK

    const int col0 = bn + wn * 64;
    #pragma unroll
    for (int mt = 0; mt < 2; mt++) {
        #pragma unroll
        for (int h = 0; h < 2; h++) {
            int row = bm + wm * 32 + mt * 16 + g + h * 8;
            float* cp = C + (size_t)row * N + col0;
            #pragma unroll
            for (int nt = 0; nt < 8; nt++) {
                int cc = nt * 8 + t * 2;
                float2 bz = *(const float2*)(bias + col0 + cc);
                float2 v;
                v.x = acc[mt][nt][h * 2 + 0] + bz.x;
                v.y = acc[mt][nt][h * 2 + 1] + bz.y;
                if (ROUND_OUT) { v.x = tf32_rna(v.x); v.y = tf32_rna(v.y); }
                *(float2*)(cp + cc) = v;
            }
        }
    }
}

// ===========================================================================
// Tensor-core flash attention. Block = (128-row q-tile, head, batch), 8 warps,
// warp owns 16 rows. K/V (64 keys/tile) cp.async double-buffered.
// exp2-domain softmax: Q pre-scaled by 0.125*log2(e), re-rounded to tf32.
// Warp-level skip of fully-masked causal tiles.
// ===========================================================================
#define QT  128
#define KST 68
#define VST 72
#define AP_OFF  0                                  // P/Q staging: 128 x KST
#define AK_OFF(s) (QT * KST + (s) * 64 * KST)      // K buffers
#define AV_OFF(s) (QT * KST + 2 * 64 * KST + (s) * 64 * VST)
#define ASMEM_BYTES ((QT * KST + 2 * 64 * KST + 2 * 64 * VST) * 4)   // 106496

__global__ __launch_bounds__(256, 2) void flash_attn_tc(const int* __restrict__ causal_flag)
{
    extern __shared__ float smf[];
    const uint32_t sb = smem_u32(smf);
    float* Ps = smf + AP_OFF;

    const int qt = blockIdx.x, h = blockIdx.y, b = blockIdx.z;
    const int tid = threadIdx.x, lane = tid & 31, w = tid >> 5;
    const int g = lane >> 2, t = lane & 3;
    const int causal = *causal_flag;
    const int r0 = w * 16 + g, r1 = r0 + 8;      // local rows (0..127)
    const int rowmin = qt * QT + w * 16;          // warp's smallest global row

    const int ktmax = causal ? min(2 * qt + 1, SS / 64 - 1) : (SS / 64 - 1);
    const float* kvb = g_qkv + (size_t)(b * SS) * N1 + DD + h * DH;
    const int irow = tid >> 4;     // 0..15
    const int ic4  = tid & 15;

    const uint32_t pAddr = sb + (uint32_t)(((w * 16 + (lane & 15)) * KST
                                            + (lane >> 4) * 4) * 4);
    const uint32_t kAddr = sb + (uint32_t)((AK_OFF(0)
                         + ((lane & 7) + ((lane & 16) >> 1)) * KST
                         + ((lane & 8) >> 1)) * 4);

#define ISSUE_KV(kt, s) do { \
    const float* _kb = kvb + (size_t)((kt) * 64) * N1; \
    uint32_t _kd = sb + (uint32_t)(AK_OFF(s) * 4); \
    uint32_t _vd = sb + (uint32_t)(AV_OFF(s) * 4); \
    _Pragma("unroll") \
    for (int _i = 0; _i < 4; _i++) { \
        int _r = irow + _i * 16; \
        const float* _src = _kb + (size_t)_r * N1 + ic4 * 4; \
        CP_A16(_kd + (uint32_t)((_r * KST + ic4 * 4) * 4), _src); \
        CP_A16(_vd + (uint32_t)((_r * VST + ic4 * 4) * 4), _src + DD); \
    } \
    CP_COMMIT(); \
} while (0)

    ISSUE_KV(0, 0);

    // stage Q * (0.125 * log2 e), re-rounded to tf32 (exp2-domain scores)
    {
        const float qs = 0.125f * 1.4426950408889634f;
        const float* qb = g_qkv + (size_t)(b * SS + qt * QT) * N1 + h * DH;
        #pragma unroll
        for (int i = 0; i < 8; i++) {
            int fid = tid + i * 256, row = fid >> 4, c4 = fid & 15;
            float4 v = *(const float4*)(qb + (size_t)row * N1 + c4 * 4);
            float* d = Ps + row * KST + c4 * 4;
            d[0] = tf32_rna(v.x * qs); d[1] = tf32_rna(v.y * qs);
            d[2] = tf32_rna(v.z * qs); d[3] = tf32_rna(v.w * qs);
        }
    }
    __syncthreads();
    uint32_t qf[8][4];
    #pragma unroll
    for (int ks = 0; ks < 8; ks++) LDSM4(qf[ks], pAddr + ks * 32);

    float m0 = -INFINITY, m1 = -INFINITY, l0 = 0.f, l1 = 0.f;
    float oa[8][4];
    #pragma unroll
    for (int nt = 0; nt < 8; nt++)
        #pragma unroll
        for (int r = 0; r < 4; r++) oa[nt][r] = 0.f;

    for (int kt = 0; kt <= ktmax; kt++) {
        const int cur = kt & 1;
        CP_WAIT0();
        __syncthreads();
        if (kt < ktmax) ISSUE_KV(kt + 1, cur ^ 1);

        // warp-level causal skip: entire warp above the diagonal for this tile
        if (causal && kt * 64 > rowmin + 15) continue;

        const float* Vs = smf + AV_OFF(cur);
        const uint32_t kOff = (uint32_t)(cur * (64 * KST * 4));

        // ---- S = Q K^T (log2-domain) ----
        float sc[8][4];
        #pragma unroll
        for (int nt = 0; nt < 8; nt++)
            #pragma unroll
            for (int r = 0; r < 4; r++) sc[nt][r] = 0.f;
        #pragma unroll
        for (int ks = 0; ks < 8; ks++) {
            uint32_t kb[4][4];
            #pragma unroll
            for (int p = 0; p < 4; p++)
                LDSM4(kb[p], kAddr + kOff + ks * 32 + p * (16 * KST * 4));
            #pragma unroll
            for (int nt = 0; nt < 8; nt++)
                MMA_TF32(sc[nt], qf[ks][0], qf[ks][1], qf[ks][2], qf[ks][3],
                         kb[nt >> 1][(nt & 1) * 2], kb[nt >> 1][(nt & 1) * 2 + 1]);
        }

        // ---- causal mask (tile crosses diagonal for this warp) ----
        if (causal && kt * 64 + 63 > rowmin) {
            const int r0g = rowmin + g, r1g = r0g + 8;
            #pragma unroll
            for (int nt = 0; nt < 8; nt++) {
                int c0 = kt * 64 + nt * 8 + 2 * t, c1 = c0 + 1;
                if (c0 > r0g) sc[nt][0] = -INFINITY;
                if (c1 > r0g) sc[nt][1] = -INFINITY;
                if (c0 > r1g) sc[nt][2] = -INFINITY;
                if (c1 > r1g) sc[nt][3] = -INFINITY;
            }
        }

        // ---- online softmax (exp2 domain) ----
        float mx0 = m0, mx1 = m1;
        #pragma unroll
        for (int nt = 0; nt < 8; nt++) {
            mx0 = fmaxf(mx0, fmaxf(sc[nt][0], sc[nt][1]));
            mx1 = fmaxf(mx1, fmaxf(sc[nt][2], sc[nt][3]));
        }
        mx0 = fmaxf(mx0, __shfl_xor_sync(0xffffffffu, mx0, 1));
        mx0 = fmaxf(mx0, __shfl_xor_sync(0xffffffffu, mx0, 2));
        mx1 = fmaxf(mx1, __shfl_xor_sync(0xffffffffu, mx1, 1));
        mx1 = fmaxf(mx1, __shfl_xor_sync(0xffffffffu, mx1, 2));
        float a0 = exp2f(m0 - mx0), a1 = exp2f(m1 - mx1);
        m0 = mx0; m1 = mx1;
        l0 *= a0; l1 *= a1;

        float s0 = 0.f, s1 = 0.f;
        #pragma unroll
        for (int nt = 0; nt < 8; nt++) {
            float p00 = exp2f(sc[nt][0] - m0);
            float p01 = exp2f(sc[nt][1] - m0);
            float p10 = exp2f(sc[nt][2] - m1);
            float p11 = exp2f(sc[nt][3] - m1);
            s0 += p00 + p01; s1 += p10 + p11;
            *(float2*)(Ps + r0 * KST + nt * 8 + 2 * t) =
                make_float2(tf32_rna(p00), tf32_rna(p01));
            *(float2*)(Ps + r1 * KST + nt * 8 + 2 * t) =
                make_float2(tf32_rna(p10), tf32_rna(p11));
            oa[nt][0] *= a0; oa[nt][1] *= a0;
            oa[nt][2] *= a1; oa[nt][3] *= a1;
        }
        s0 += __shfl_xor_sync(0xffffffffu, s0, 1);
        s0 += __shfl_xor_sync(0xffffffffu, s0, 2);
        s1 += __shfl_xor_sync(0xffffffffu, s1, 1);
        s1 += __shfl_xor_sync(0xffffffffu, s1, 2);
        l0 += s0; l1 += s1;
        __syncwarp();

        // ---- O += P V  (V row-major [key][d], stride VST) ----
        #pragma unroll
        for (int ks = 0; ks < 8; ks++) {
            uint32_t pf[4];
            LDSM4(pf, pAddr + ks * 32);
            #pragma unroll
            for (int nt = 0; nt < 8; nt++) {
                uint32_t b0 = __float_as_uint(Vs[(ks * 8 + t) * VST + nt * 8 + g]);
                uint32_t b1 = __float_as_uint(Vs[(ks * 8 + t + 4) * VST + nt * 8 + g]);
                MMA_TF32(oa[nt], pf[0], pf[1], pf[2], pf[3], b0, b1);
            }
        }
        __syncwarp();
    }
#undef ISSUE_KV

    float i0 = 1.f / l0, i1 = 1.f / l1;
    float* ob = g_att + (size_t)(b * SS + qt * QT) * DD + h * DH;
    #pragma unroll
    for (int nt = 0; nt < 8; nt++) {
        *(float2*)(ob + (size_t)r0 * DD + nt * 8 + 2 * t) =
            make_float2(tf32_rna(oa[nt][0] * i0), tf32_rna(oa[nt][1] * i0));
        *(float2*)(ob + (size_t)r1 * DD + nt * 8 + 2 * t) =
            make_float2(tf32_rna(oa[nt][2] * i1), tf32_rna(oa[nt][3] * i1));
    }
}

// ---------------------------------------------------------------------------
extern "C" void kernel_launch(void* const* d_in, const int* in_sizes, int n_in,
                              void* d_out, int out_size)
{
    const float* x     = (const float*)d_in[0];
    const float* w_in  = (const float*)d_in[1];
    const float* b_in  = (const float*)d_in[2];
    const float* w_out = (const float*)d_in[3];
    const float* b_out = (const float*)d_in[4];
    const int*   cmask = (const int*)d_in[5];
    float* out = (float*)d_out;

    float *qkv, *att, *xr, *w1r, *w2r;
    cudaGetSymbolAddress((void**)&qkv, g_qkv);
    cudaGetSymbolAddress((void**)&att, g_att);
    cudaGetSymbolAddress((void**)&xr,  g_xr);
    cudaGetSymbolAddress((void**)&w1r, g_w1r);
    cudaGetSymbolAddress((void**)&w2r, g_w2r);

    cudaFuncSetAttribute(gemm_tf32mma<1>,
                         cudaFuncAttributeMaxDynamicSharedMemorySize, GSMEM_BYTES);
    cudaFuncSetAttribute(gemm_tf32mma<0>,
                         cudaFuncAttributeMaxDynamicSharedMemorySize, GSMEM_BYTES);
    cudaFuncSetAttribute(flash_attn_tc,
                         cudaFuncAttributeMaxDynamicSharedMemorySize, ASMEM_BYTES);

    // 0) round x, w_in, w_out to tf32-exact fp32 (one launch)
    {
        int tot = MROWS * DD / 4 + N1 * DD / 4 + DD * DD / 4;
        round3_tf32<<<(tot + 255) / 256, 256>>>(x, xr, w_in, w1r, w_out, w2r);
    }

    // 1) QKV projection (output rounded for the attention stage)
    gemm_tf32mma<1><<<dim3(N1 / 128, MROWS / 128), 256, GSMEM_BYTES>>>(
        xr, w1r, b_in, qkv, MROWS, N1, DD);

    // 2) Causal multi-head flash attention (tensor cores, 128-row q-tiles)
    flash_attn_tc<<<dim3(SS / QT, HH, BB), 256, ASMEM_BYTES>>>(cmask);

    // 3) Output projection (plain fp32 output)
    gemm_tf32mma<0><<<dim3(DD / 128, MROWS / 128), 256, GSMEM_BYTES>>>(
        att, w2r, b_out, out, MROWS, DD, DD);
}